// round 1
// baseline (speedup 1.0000x reference)
#include <cuda_runtime.h>

#define HEADSZ 64
#define EMB    1024
#define BATCH  4
#define SEQ    4096
#define BT     (BATCH*SEQ)
#define DS     256   // dim slice per attn_out block

// Scratch (allocation-free): projections + softmax stats
__device__ float g_K[(size_t)BT*HEADSZ];
__device__ float g_Q[(size_t)BT*HEADSZ];
__device__ float g_V[(size_t)BT*EMB];
__device__ float g_M[BT];
__device__ float g_L[BT];

// ---------------------------------------------------------------------------
// C[M,N] = A[M,Kd] @ W[N,Kd]^T   (row-major A, W as [out,in] like nn.Linear)
// 64x64 block tile, BK=16, 256 threads, 4x4 per-thread microtile.
// ---------------------------------------------------------------------------
__global__ __launch_bounds__(256) void gemm_xwT(
    const float* __restrict__ A, const float* __restrict__ W,
    float* __restrict__ C, int M, int N, int Kd)
{
    __shared__ float As[64][17];
    __shared__ float Ws[64][17];
    const int tid = threadIdx.x;
    const int tx = tid & 15, ty = tid >> 4;
    const int row0 = blockIdx.y * 64;
    const int col0 = blockIdx.x * 64;

    float acc[4][4];
    #pragma unroll
    for (int u = 0; u < 4; u++)
        #pragma unroll
        for (int v = 0; v < 4; v++) acc[u][v] = 0.f;

    for (int k0 = 0; k0 < Kd; k0 += 16) {
        #pragma unroll
        for (int i = tid; i < 64*16; i += 256) {
            int r = i >> 4, c = i & 15;
            As[r][c] = A[(size_t)(row0 + r) * Kd + k0 + c];
        }
        #pragma unroll
        for (int i = tid; i < 64*16; i += 256) {
            int r = i >> 4, c = i & 15;
            Ws[r][c] = W[(size_t)(col0 + r) * Kd + k0 + c];
        }
        __syncthreads();
        #pragma unroll
        for (int kk = 0; kk < 16; kk++) {
            float a[4], b[4];
            #pragma unroll
            for (int u = 0; u < 4; u++) a[u] = As[ty*4+u][kk];
            #pragma unroll
            for (int v = 0; v < 4; v++) b[v] = Ws[tx*4+v][kk];
            #pragma unroll
            for (int u = 0; u < 4; u++)
                #pragma unroll
                for (int v = 0; v < 4; v++)
                    acc[u][v] = fmaf(a[u], b[v], acc[u][v]);
        }
        __syncthreads();
    }
    #pragma unroll
    for (int u = 0; u < 4; u++)
        #pragma unroll
        for (int v = 0; v < 4; v++)
            C[(size_t)(row0 + ty*4+u) * N + col0 + tx*4+v] = acc[u][v];
}

// ---------------------------------------------------------------------------
// Pass A: per-row softmax stats (running max m, running denom l), causal.
// One block = 64 queries of one batch. 256 threads, 4x4 scores per thread.
// ---------------------------------------------------------------------------
__global__ __launch_bounds__(256) void attn_stats(
    const float* __restrict__ Qb, const float* __restrict__ Kb,
    float* __restrict__ Mo, float* __restrict__ Lo)
{
    __shared__ float Qs[64][HEADSZ+1];
    __shared__ float Ks[64][HEADSZ+1];
    __shared__ float rm[64], rl[64];

    const int tid = threadIdx.x, tx = tid & 15, ty = tid >> 4;
    const int qtile = blockIdx.x;
    const int b  = qtile / (SEQ/64);
    const int q0 = (qtile % (SEQ/64)) * 64;
    const float* Qbase = Qb + (size_t)(b*SEQ + q0) * HEADSZ;
    const float* Kbase = Kb + (size_t)b * SEQ * HEADSZ;

    #pragma unroll
    for (int i = tid; i < 64*HEADSZ; i += 256)
        Qs[i>>6][i&63] = Qbase[i];
    if (tid < 64) { rm[tid] = -1e30f; rl[tid] = 0.f; }
    __syncthreads();

    const int nkt = q0/64 + 1;
    for (int kt = 0; kt < nkt; kt++) {
        #pragma unroll
        for (int i = tid; i < 64*HEADSZ; i += 256)
            Ks[i>>6][i&63] = Kbase[(size_t)kt*64*HEADSZ + i];
        __syncthreads();

        float s[4][4];
        #pragma unroll
        for (int u = 0; u < 4; u++)
            #pragma unroll
            for (int v = 0; v < 4; v++) s[u][v] = 0.f;

        #pragma unroll 8
        for (int d = 0; d < HEADSZ; d++) {
            float a[4], bb[4];
            #pragma unroll
            for (int u = 0; u < 4; u++) a[u] = Qs[ty*4+u][d];
            #pragma unroll
            for (int v = 0; v < 4; v++) bb[v] = Ks[tx*4+v][d];
            #pragma unroll
            for (int u = 0; u < 4; u++)
                #pragma unroll
                for (int v = 0; v < 4; v++)
                    s[u][v] = fmaf(a[u], bb[v], s[u][v]);
        }

        const bool diag = (kt == nkt - 1);
        #pragma unroll
        for (int u = 0; u < 4; u++) {
            const int qi = q0 + ty*4 + u;
            #pragma unroll
            for (int v = 0; v < 4; v++) {
                const int kj = kt*64 + tx*4 + v;
                s[u][v] *= 0.125f;               // 1/sqrt(64)
                if (diag && kj > qi) s[u][v] = -1e30f;
            }
        }

        float newm[4], ps[4];
        #pragma unroll
        for (int u = 0; u < 4; u++) {
            float tm = fmaxf(fmaxf(s[u][0], s[u][1]), fmaxf(s[u][2], s[u][3]));
            for (int off = 8; off; off >>= 1)
                tm = fmaxf(tm, __shfl_xor_sync(0xffffffffu, tm, off));
            newm[u] = fmaxf(rm[ty*4+u], tm);
            float p = 0.f;
            #pragma unroll
            for (int v = 0; v < 4; v++) p += __expf(s[u][v] - newm[u]);
            for (int off = 8; off; off >>= 1)
                p += __shfl_xor_sync(0xffffffffu, p, off);
            ps[u] = p;
        }
        if (tx == 0) {
            #pragma unroll
            for (int u = 0; u < 4; u++) {
                const int r = ty*4 + u;
                rl[r] = rl[r] * __expf(rm[r] - newm[u]) + ps[u];
                rm[r] = newm[u];
            }
        }
        __syncthreads();
    }
    if (tid < 64) {
        Mo[(size_t)b*SEQ + q0 + tid] = rm[tid];
        Lo[(size_t)b*SEQ + q0 + tid] = rl[tid];
    }
}

// ---------------------------------------------------------------------------
// Pass B: out[b, q0:q0+64, d0:d0+DS] = softmax(QK^T) @ V slice.
// Recomputes S per dim-slice using precomputed (m, l). 256 threads.
// Accumulators: 4 rows x 16 strided cols per thread (64 regs).
// ---------------------------------------------------------------------------
#define SMEM_B_FLOATS (64*65 + 64*65 + 64*68 + 64*DS + 128)
#define SMEM_B_BYTES  (SMEM_B_FLOATS * 4)

__global__ __launch_bounds__(256, 1) void attn_out(
    const float* __restrict__ Qb, const float* __restrict__ Kb,
    const float* __restrict__ Vb, const float* __restrict__ Mo,
    const float* __restrict__ Lo, float* __restrict__ out)
{
    extern __shared__ float smbuf[];
    float* Qs  = smbuf;              // [64][65]
    float* Ks  = Qs + 64*65;         // [64][65]
    float* Pt  = Ks + 64*65;         // [64][68]  P transposed (key-major rows)
    float* Vs  = Pt + 64*68;         // [64][DS]
    float* rm  = Vs + 64*DS;         // [64]
    float* ril = rm + 64;            // [64]

    const int tid = threadIdx.x, tx = tid & 15, ty = tid >> 4;
    const int b  = blockIdx.z;
    const int q0 = blockIdx.y * 64;
    const int d0 = blockIdx.x * DS;
    const float* Qbase = Qb + (size_t)(b*SEQ + q0) * HEADSZ;
    const float* Kbase = Kb + (size_t)b * SEQ * HEADSZ;
    const float* Vbase = Vb + (size_t)b * SEQ * EMB + d0;

    #pragma unroll
    for (int i = tid; i < 64*HEADSZ; i += 256)
        Qs[(i>>6)*65 + (i&63)] = Qbase[i];
    if (tid < 64) {
        rm[tid]  = Mo[(size_t)b*SEQ + q0 + tid];
        ril[tid] = 1.0f / Lo[(size_t)b*SEQ + q0 + tid];
    }
    __syncthreads();

    float o[4][16];
    #pragma unroll
    for (int u = 0; u < 4; u++)
        #pragma unroll
        for (int w = 0; w < 16; w++) o[u][w] = 0.f;

    const int nkt = q0/64 + 1;
    for (int kt = 0; kt < nkt; kt++) {
        #pragma unroll
        for (int i = tid; i < 64*HEADSZ; i += 256)
            Ks[(i>>6)*65 + (i&63)] = Kbase[(size_t)kt*64*HEADSZ + i];
        // V tile 64 x DS, vectorized
        #pragma unroll
        for (int j = tid; j < 64*(DS/4); j += 256) {
            int r = j / (DS/4), c = j % (DS/4);
            ((float4*)Vs)[r*(DS/4) + c] =
                *(const float4*)(Vbase + (size_t)(kt*64 + r)*EMB + c*4);
        }
        __syncthreads();

        // S = Q K^T (scaled, masked), then P = exp(S - m)
        float s[4][4];
        #pragma unroll
        for (int u = 0; u < 4; u++)
            #pragma unroll
            for (int v = 0; v < 4; v++) s[u][v] = 0.f;
        #pragma unroll 8
        for (int d = 0; d < HEADSZ; d++) {
            float a[4], bb[4];
            #pragma unroll
            for (int u = 0; u < 4; u++) a[u] = Qs[(ty*4+u)*65 + d];
            #pragma unroll
            for (int v = 0; v < 4; v++) bb[v] = Ks[(tx*4+v)*65 + d];
            #pragma unroll
            for (int u = 0; u < 4; u++)
                #pragma unroll
                for (int v = 0; v < 4; v++)
                    s[u][v] = fmaf(a[u], bb[v], s[u][v]);
        }
        const bool diag = (kt == nkt - 1);
        #pragma unroll
        for (int u = 0; u < 4; u++) {
            const int qi = q0 + ty*4 + u;
            const float m = rm[ty*4+u];
            #pragma unroll
            for (int v = 0; v < 4; v++) {
                const int kj = kt*64 + tx*4 + v;
                float sv = s[u][v] * 0.125f;
                if (diag && kj > qi) sv = -1e30f;
                s[u][v] = __expf(sv - m);
            }
        }
        #pragma unroll
        for (int v = 0; v < 4; v++)
            #pragma unroll
            for (int u = 0; u < 4; u++)
                Pt[(tx*4+v)*68 + ty*4+u] = s[u][v];
        __syncthreads();

        // O += P @ V_slice
        #pragma unroll 8
        for (int k = 0; k < 64; k++) {
            const float4 p4 = *(const float4*)&Pt[k*68 + ty*4];
            #pragma unroll
            for (int w = 0; w < 16; w++) {
                const float vv = Vs[k*DS + tx + 16*w];
                o[0][w] = fmaf(p4.x, vv, o[0][w]);
                o[1][w] = fmaf(p4.y, vv, o[1][w]);
                o[2][w] = fmaf(p4.z, vv, o[2][w]);
                o[3][w] = fmaf(p4.w, vv, o[3][w]);
            }
        }
        __syncthreads();
    }

    #pragma unroll
    for (int u = 0; u < 4; u++) {
        const int i = ty*4 + u;
        const float inv = ril[i];
        const size_t base = (size_t)(b*SEQ + q0 + i) * EMB + d0;
        #pragma unroll
        for (int w = 0; w < 16; w++)
            out[base + tx + 16*w] = o[u][w] * inv;
    }
}

// ---------------------------------------------------------------------------
extern "C" void kernel_launch(void* const* d_in, const int* in_sizes, int n_in,
                              void* d_out, int out_size)
{
    const float* x  = (const float*)d_in[0];  // [B,T,D]
    const float* Wk = (const float*)d_in[1];  // [H,D]
    const float* Wq = (const float*)d_in[2];  // [H,D]
    const float* Wv = (const float*)d_in[3];  // [D,D]
    float* out = (float*)d_out;

    float *Kp, *Qp, *Vp, *Mp, *Lp;
    cudaGetSymbolAddress((void**)&Kp, g_K);
    cudaGetSymbolAddress((void**)&Qp, g_Q);
    cudaGetSymbolAddress((void**)&Vp, g_V);
    cudaGetSymbolAddress((void**)&Mp, g_M);
    cudaGetSymbolAddress((void**)&Lp, g_L);

    // Projections
    gemm_xwT<<<dim3(EMB/64, BT/64), 256>>>(x, Wv, Vp, BT, EMB, EMB);
    gemm_xwT<<<dim3(HEADSZ/64, BT/64), 256>>>(x, Wk, Kp, BT, HEADSZ, EMB);
    gemm_xwT<<<dim3(HEADSZ/64, BT/64), 256>>>(x, Wq, Qp, BT, HEADSZ, EMB);

    // Softmax stats
    attn_stats<<<BT/64, 256>>>(Qp, Kp, Mp, Lp);

    // Output
    cudaFuncSetAttribute(attn_out, cudaFuncAttributeMaxDynamicSharedMemorySize,
                         SMEM_B_BYTES);
    attn_out<<<dim3(EMB/DS, SEQ/64, BATCH), 256, SMEM_B_BYTES>>>(
        Qp, Kp, Vp, Mp, Lp, out);
}

// round 4
// speedup vs baseline: 1.7517x; 1.7517x over previous
#include <cuda_runtime.h>
#include <cuda_bf16.h>
#include <cstdint>

#define HEADSZ 64
#define EMB    1024
#define BATCH  4
#define SEQ    4096
#define BT     (BATCH*SEQ)

// Scratch (allocation-free)
__device__ float g_K[(size_t)BT*HEADSZ];
__device__ float g_Q[(size_t)BT*HEADSZ];
__device__ float g_V[(size_t)BT*EMB];
__device__ float g_M[BT];
__device__ float g_L[BT];

// ===========================================================================
// helpers
// ===========================================================================
__device__ __forceinline__ uint32_t smem_u32(const void* p) {
    uint32_t a;
    asm("{ .reg .u64 t; cvta.to.shared.u64 t, %1; cvt.u32.u64 %0, t; }"
        : "=r"(a) : "l"(p));
    return a;
}

#define LDMX4(r, a) \
    asm volatile("ldmatrix.sync.aligned.m8n8.x4.shared.b16 {%0,%1,%2,%3}, [%4];" \
        : "=r"((r)[0]), "=r"((r)[1]), "=r"((r)[2]), "=r"((r)[3]) : "r"(a))
#define LDMX2(r, a) \
    asm volatile("ldmatrix.sync.aligned.m8n8.x2.shared.b16 {%0,%1}, [%2];" \
        : "=r"((r)[0]), "=r"((r)[1]) : "r"(a))

#define MMA_BF16(d, a, b) \
    asm volatile("mma.sync.aligned.m16n8k16.row.col.f32.bf16.bf16.f32 " \
        "{%0,%1,%2,%3}, {%4,%5,%6,%7}, {%8,%9}, {%0,%1,%2,%3};" \
        : "+f"((d)[0]), "+f"((d)[1]), "+f"((d)[2]), "+f"((d)[3]) \
        : "r"((a)[0]), "r"((a)[1]), "r"((a)[2]), "r"((a)[3]), \
          "r"((b)[0]), "r"((b)[1]))

#define MMA3(d, ah, al, bh, bl) do { \
    MMA_BF16(d, ah, bh); MMA_BF16(d, ah, bl); MMA_BF16(d, al, bh); } while (0)

// A-fragment ldmatrix address (m16 x k16, [row][k] layout, strideB bytes/row)
__device__ __forceinline__ uint32_t a_addr(uint32_t base, int row, int kbyte,
                                           int lane, int strideB) {
    return base + (uint32_t)(row + (lane & 15)) * strideB + kbyte +
           ((lane >> 4) << 4);
}
// B-fragment ldmatrix address (k16 x n8, [n][k] layout)
__device__ __forceinline__ uint32_t b_addr(uint32_t base, int row, int kbyte,
                                           int lane, int strideB) {
    return base + (uint32_t)(row + (lane & 7)) * strideB + kbyte +
           (((lane >> 3) & 1) << 4);
}

__device__ __forceinline__ uint32_t bpack(__nv_bfloat16 a, __nv_bfloat16 b) {
    return ((uint32_t)__bfloat16_as_ushort(b) << 16) |
           (uint32_t)__bfloat16_as_ushort(a);
}

// Split a float4 (4 consecutive k-elements) into hi/lo bf16 pairs; store 8B each.
__device__ __forceinline__ void split_store4(float4 v, char* ph, char* pl) {
    __nv_bfloat16 hx = __float2bfloat16_rn(v.x), hy = __float2bfloat16_rn(v.y);
    __nv_bfloat16 hz = __float2bfloat16_rn(v.z), hw = __float2bfloat16_rn(v.w);
    __nv_bfloat16 lx = __float2bfloat16_rn(v.x - __bfloat162float(hx));
    __nv_bfloat16 ly = __float2bfloat16_rn(v.y - __bfloat162float(hy));
    __nv_bfloat16 lz = __float2bfloat16_rn(v.z - __bfloat162float(hz));
    __nv_bfloat16 lw = __float2bfloat16_rn(v.w - __bfloat162float(hw));
    uint2 h; h.x = bpack(hx, hy); h.y = bpack(hz, hw);
    uint2 l; l.x = bpack(lx, ly); l.y = bpack(lz, lw);
    *(uint2*)ph = h;
    *(uint2*)pl = l;
}

// ===========================================================================
// Fused Q/K projection: g_K = x@Wk^T, g_Q = x@Wq^T  (bf16x3 mma)
// CTA tile 128 rows x 128 cols (cols 0-63 -> K, 64-127 -> Q). BK=32.
// ===========================================================================
#define PJ_STRIDE 80            // bytes per row (40 bf16)
#define PJ_AH 0
#define PJ_AL 10240
#define PJ_BH 20480
#define PJ_BL 30720
#define PJ_SMEM 40960

__global__ __launch_bounds__(256, 1) void qkproj_mma(
    const float* __restrict__ A, const float* __restrict__ Wk,
    const float* __restrict__ Wq, float* __restrict__ Ck,
    float* __restrict__ Cq)
{
    extern __shared__ char sm[];
    const uint32_t smb = smem_u32(sm);
    const int tid = threadIdx.x, wid = tid >> 5, lane = tid & 31;
    const int g = lane >> 2, t = lane & 3;
    const int row0 = blockIdx.y * 128;
    const int m0 = (wid & 3) * 32, n0 = (wid >> 2) * 64;

    float o[16][4];
    #pragma unroll
    for (int i = 0; i < 16; i++)
        #pragma unroll
        for (int j = 0; j < 4; j++) o[i][j] = 0.f;

    const int lr = tid >> 1, lc0 = (tid & 1) * 16;
    const float* arow = A + (size_t)(row0 + lr) * EMB + lc0;
    const float* brow = (lr < 64 ? Wk + (size_t)lr * EMB
                                 : Wq + (size_t)(lr - 64) * EMB) + lc0;

    for (int kc = 0; kc < EMB / 32; kc++) {
        #pragma unroll
        for (int j = 0; j < 4; j++) {
            float4 va = *(const float4*)(arow + kc * 32 + j * 4);
            split_store4(va, sm + PJ_AH + lr * PJ_STRIDE + lc0 * 2 + j * 8,
                             sm + PJ_AL + lr * PJ_STRIDE + lc0 * 2 + j * 8);
            float4 vb = *(const float4*)(brow + kc * 32 + j * 4);
            split_store4(vb, sm + PJ_BH + lr * PJ_STRIDE + lc0 * 2 + j * 8,
                             sm + PJ_BL + lr * PJ_STRIDE + lc0 * 2 + j * 8);
        }
        __syncthreads();
        #pragma unroll
        for (int ks = 0; ks < 2; ks++) {
            uint32_t ah[2][4], al[2][4];
            #pragma unroll
            for (int mt = 0; mt < 2; mt++) {
                LDMX4(ah[mt], a_addr(smb + PJ_AH, m0 + mt*16, ks*32, lane, PJ_STRIDE));
                LDMX4(al[mt], a_addr(smb + PJ_AL, m0 + mt*16, ks*32, lane, PJ_STRIDE));
            }
            #pragma unroll
            for (int nt = 0; nt < 8; nt++) {
                uint32_t bh[2], bl[2];
                LDMX2(bh, b_addr(smb + PJ_BH, n0 + nt*8, ks*32, lane, PJ_STRIDE));
                LDMX2(bl, b_addr(smb + PJ_BL, n0 + nt*8, ks*32, lane, PJ_STRIDE));
                #pragma unroll
                for (int mt = 0; mt < 2; mt++)
                    MMA3(o[mt*8 + nt], ah[mt], al[mt], bh, bl);
            }
        }
        __syncthreads();
    }

    float* Cp = (n0 == 0) ? Ck : Cq;
    #pragma unroll
    for (int mt = 0; mt < 2; mt++)
        #pragma unroll
        for (int nt = 0; nt < 8; nt++) {
            const int r0 = row0 + m0 + mt*16 + g;
            const int c  = nt*8 + 2*t;
            float2 v0 = make_float2(o[mt*8+nt][0], o[mt*8+nt][1]);
            float2 v1 = make_float2(o[mt*8+nt][2], o[mt*8+nt][3]);
            *(float2*)(Cp + (size_t)r0 * HEADSZ + c)       = v0;
            *(float2*)(Cp + (size_t)(r0 + 8) * HEADSZ + c) = v1;
        }
}

// ===========================================================================
// V projection: g_V = x@Wv^T  (bf16x3 mma), tile 128x128, BK=32
// ===========================================================================
__global__ __launch_bounds__(256, 1) void vproj_mma(
    const float* __restrict__ A, const float* __restrict__ W,
    float* __restrict__ C)
{
    extern __shared__ char sm[];
    const uint32_t smb = smem_u32(sm);
    const int tid = threadIdx.x, wid = tid >> 5, lane = tid & 31;
    const int g = lane >> 2, t = lane & 3;
    const int row0 = blockIdx.y * 128;
    const int col0 = blockIdx.x * 128;
    const int m0 = (wid & 3) * 32, n0 = (wid >> 2) * 64;

    float o[16][4];
    #pragma unroll
    for (int i = 0; i < 16; i++)
        #pragma unroll
        for (int j = 0; j < 4; j++) o[i][j] = 0.f;

    const int lr = tid >> 1, lc0 = (tid & 1) * 16;
    const float* arow = A + (size_t)(row0 + lr) * EMB + lc0;
    const float* brow = W + (size_t)(col0 + lr) * EMB + lc0;

    for (int kc = 0; kc < EMB / 32; kc++) {
        #pragma unroll
        for (int j = 0; j < 4; j++) {
            float4 va = *(const float4*)(arow + kc * 32 + j * 4);
            split_store4(va, sm + PJ_AH + lr * PJ_STRIDE + lc0 * 2 + j * 8,
                             sm + PJ_AL + lr * PJ_STRIDE + lc0 * 2 + j * 8);
            float4 vb = *(const float4*)(brow + kc * 32 + j * 4);
            split_store4(vb, sm + PJ_BH + lr * PJ_STRIDE + lc0 * 2 + j * 8,
                             sm + PJ_BL + lr * PJ_STRIDE + lc0 * 2 + j * 8);
        }
        __syncthreads();
        #pragma unroll
        for (int ks = 0; ks < 2; ks++) {
            uint32_t ah[2][4], al[2][4];
            #pragma unroll
            for (int mt = 0; mt < 2; mt++) {
                LDMX4(ah[mt], a_addr(smb + PJ_AH, m0 + mt*16, ks*32, lane, PJ_STRIDE));
                LDMX4(al[mt], a_addr(smb + PJ_AL, m0 + mt*16, ks*32, lane, PJ_STRIDE));
            }
            #pragma unroll
            for (int nt = 0; nt < 8; nt++) {
                uint32_t bh[2], bl[2];
                LDMX2(bh, b_addr(smb + PJ_BH, n0 + nt*8, ks*32, lane, PJ_STRIDE));
                LDMX2(bl, b_addr(smb + PJ_BL, n0 + nt*8, ks*32, lane, PJ_STRIDE));
                #pragma unroll
                for (int mt = 0; mt < 2; mt++)
                    MMA3(o[mt*8 + nt], ah[mt], al[mt], bh, bl);
            }
        }
        __syncthreads();
    }

    #pragma unroll
    for (int mt = 0; mt < 2; mt++)
        #pragma unroll
        for (int nt = 0; nt < 8; nt++) {
            const int r0 = row0 + m0 + mt*16 + g;
            const int c  = col0 + n0 + nt*8 + 2*t;
            float2 v0 = make_float2(o[mt*8+nt][0], o[mt*8+nt][1]);
            float2 v1 = make_float2(o[mt*8+nt][2], o[mt*8+nt][3]);
            *(float2*)(C + (size_t)r0 * EMB + c)       = v0;
            *(float2*)(C + (size_t)(r0 + 8) * EMB + c) = v1;
        }
}

// ===========================================================================
// Pass A: per-row softmax stats (fp32, exact) — unchanged
// ===========================================================================
__global__ __launch_bounds__(256) void attn_stats(
    const float* __restrict__ Qb, const float* __restrict__ Kb,
    float* __restrict__ Mo, float* __restrict__ Lo)
{
    __shared__ float Qs[64][HEADSZ+1];
    __shared__ float Ks[64][HEADSZ+1];
    __shared__ float rm[64], rl[64];

    const int tid = threadIdx.x, tx = tid & 15, ty = tid >> 4;
    const int nq = SEQ/64;
    const int b  = blockIdx.x / nq;
    const int q0 = (nq - 1 - (blockIdx.x % nq)) * 64;
    const float* Qbase = Qb + (size_t)(b*SEQ + q0) * HEADSZ;
    const float* Kbase = Kb + (size_t)b * SEQ * HEADSZ;

    #pragma unroll
    for (int i = tid; i < 64*HEADSZ; i += 256)
        Qs[i>>6][i&63] = Qbase[i];
    if (tid < 64) { rm[tid] = -1e30f; rl[tid] = 0.f; }
    __syncthreads();

    const int nkt = q0/64 + 1;
    for (int kt = 0; kt < nkt; kt++) {
        #pragma unroll
        for (int i = tid; i < 64*HEADSZ; i += 256)
            Ks[i>>6][i&63] = Kbase[(size_t)kt*64*HEADSZ + i];
        __syncthreads();

        float s[4][4];
        #pragma unroll
        for (int u = 0; u < 4; u++)
            #pragma unroll
            for (int v = 0; v < 4; v++) s[u][v] = 0.f;

        #pragma unroll 8
        for (int d = 0; d < HEADSZ; d++) {
            float a[4], bb[4];
            #pragma unroll
            for (int u = 0; u < 4; u++) a[u] = Qs[ty*4+u][d];
            #pragma unroll
            for (int v = 0; v < 4; v++) bb[v] = Ks[tx*4+v][d];
            #pragma unroll
            for (int u = 0; u < 4; u++)
                #pragma unroll
                for (int v = 0; v < 4; v++)
                    s[u][v] = fmaf(a[u], bb[v], s[u][v]);
        }

        const bool diag = (kt == nkt - 1);
        #pragma unroll
        for (int u = 0; u < 4; u++) {
            const int qi = q0 + ty*4 + u;
            #pragma unroll
            for (int v = 0; v < 4; v++) {
                const int kj = kt*64 + tx*4 + v;
                s[u][v] *= 0.125f;
                if (diag && kj > qi) s[u][v] = -1e30f;
            }
        }

        float newm[4], ps[4];
        #pragma unroll
        for (int u = 0; u < 4; u++) {
            float tm = fmaxf(fmaxf(s[u][0], s[u][1]), fmaxf(s[u][2], s[u][3]));
            for (int off = 8; off; off >>= 1)
                tm = fmaxf(tm, __shfl_xor_sync(0xffffffffu, tm, off));
            newm[u] = fmaxf(rm[ty*4+u], tm);
            float p = 0.f;
            #pragma unroll
            for (int v = 0; v < 4; v++) p += __expf(s[u][v] - newm[u]);
            for (int off = 8; off; off >>= 1)
                p += __shfl_xor_sync(0xffffffffu, p, off);
            ps[u] = p;
        }
        if (tx == 0) {
            #pragma unroll
            for (int u = 0; u < 4; u++) {
                const int r = ty*4 + u;
                rl[r] = rl[r] * __expf(rm[r] - newm[u]) + ps[u];
                rm[r] = newm[u];
            }
        }
        __syncthreads();
    }
    if (tid < 64) {
        Mo[(size_t)b*SEQ + q0 + tid] = rm[tid];
        Lo[(size_t)b*SEQ + q0 + tid] = rl[tid];
    }
}

// ===========================================================================
// Pass B on mma.sync (bf16x3). Per CTA: 128 queries x 128 output dims.
// Per 64-key tile: S = Q@K^T (mma) -> exp/mask (regs, precomputed m)
//                  -> P split to smem -> O += P@Vt^T (mma).
// ===========================================================================
#define AT_STRIDE 144          // bytes per operand row (72 bf16)
#define AT_RM   0
#define AT_RIL  512
#define AT_QH   1024
#define AT_QL   (AT_QH  + 128*AT_STRIDE)   // 19456
#define AT_KH   (AT_QL  + 128*AT_STRIDE)   // 37888
#define AT_KL   (AT_KH  +  64*AT_STRIDE)   // 47104
#define AT_VTH  (AT_KL  +  64*AT_STRIDE)   // 56320
#define AT_VTL  (AT_VTH + 128*AT_STRIDE)   // 74752
#define AT_PH   (AT_VTL + 128*AT_STRIDE)   // 93184
#define AT_PL   (AT_PH  + 128*AT_STRIDE)   // 111616
#define AT_SMEM (AT_PL  + 128*AT_STRIDE)   // 130048

__global__ __launch_bounds__(256, 1) void attn_mma(
    const float* __restrict__ Qb, const float* __restrict__ Kb,
    const float* __restrict__ Vb, const float* __restrict__ Mo,
    const float* __restrict__ Lo, float* __restrict__ out)
{
    extern __shared__ char sm[];
    const uint32_t smb = smem_u32(sm);
    float* smf = (float*)sm;
    const int tid = threadIdx.x, wid = tid >> 5, lane = tid & 31;
    const int g = lane >> 2, t = lane & 3;
    const int b  = blockIdx.z;
    const int qt = (SEQ/128 - 1) - blockIdx.y;
    const int q0 = qt * 128;
    const int d0 = blockIdx.x * 128;

    const float* Qbase = Qb + (size_t)(b*SEQ + q0) * HEADSZ;
    const float* Kbase = Kb + (size_t)b * SEQ * HEADSZ;
    const float* Vbase = Vb + (size_t)b * SEQ * EMB + d0;

    if (tid < 128) {
        smf[AT_RM/4  + tid] = Mo[(size_t)b*SEQ + q0 + tid];
        smf[AT_RIL/4 + tid] = 1.0f / Lo[(size_t)b*SEQ + q0 + tid];
    }
    // Q tile 128x64 -> split bf16
    {
        const int r = tid >> 1, c0 = (tid & 1) * 32;
        const float* qr = Qbase + (size_t)r * HEADSZ + c0;
        #pragma unroll
        for (int j = 0; j < 8; j++) {
            float4 v = *(const float4*)(qr + j*4);
            split_store4(v, sm + AT_QH + r*AT_STRIDE + c0*2 + j*8,
                            sm + AT_QL + r*AT_STRIDE + c0*2 + j*8);
        }
    }
    __syncthreads();

    // hoisted row constants
    const int m0s = wid * 16;                       // S-phase rows
    const float mA = smf[AT_RM/4 + m0s + g];
    const float mB = smf[AT_RM/4 + m0s + 8 + g];
    const int m0p = (wid & 3) * 32;                 // PV-phase rows
    const int n0p = (wid >> 2) * 64;                // PV-phase cols

    float o[16][4];
    #pragma unroll
    for (int i = 0; i < 16; i++)
        #pragma unroll
        for (int j = 0; j < 4; j++) o[i][j] = 0.f;

    const int nkt = 2*qt + 2;
    for (int kt = 0; kt < nkt; kt++) {
        // K tile 64x64 -> split
        {
            const int r = tid >> 2, c0 = (tid & 3) * 16;
            const float* kr = Kbase + (size_t)(kt*64 + r) * HEADSZ + c0;
            #pragma unroll
            for (int j = 0; j < 4; j++) {
                float4 v = *(const float4*)(kr + j*4);
                split_store4(v, sm + AT_KH + r*AT_STRIDE + c0*2 + j*8,
                                sm + AT_KL + r*AT_STRIDE + c0*2 + j*8);
            }
        }
        // V tile 64x128 -> transpose -> Vt[dim][key] split
        {
            const float* v0 = Vbase + (size_t)(kt*64 + 2*lane) * EMB + wid*16;
            const float* v1 = v0 + EMB;
            #pragma unroll
            for (int j = 0; j < 4; j++) {
                float4 a = *(const float4*)(v0 + j*4);
                float4 c = *(const float4*)(v1 + j*4);
                const float pa[4] = {a.x, a.y, a.z, a.w};
                const float pc[4] = {c.x, c.y, c.z, c.w};
                #pragma unroll
                for (int e = 0; e < 4; e++) {
                    const int dim = wid*16 + j*4 + e;
                    __nv_bfloat16 h0 = __float2bfloat16_rn(pa[e]);
                    __nv_bfloat16 h1 = __float2bfloat16_rn(pc[e]);
                    __nv_bfloat16 l0 = __float2bfloat16_rn(pa[e] - __bfloat162float(h0));
                    __nv_bfloat16 l1 = __float2bfloat16_rn(pc[e] - __bfloat162float(h1));
                    *(uint32_t*)(sm + AT_VTH + dim*AT_STRIDE + lane*4) = bpack(h0, h1);
                    *(uint32_t*)(sm + AT_VTL + dim*AT_STRIDE + lane*4) = bpack(l0, l1);
                }
            }
        }
        __syncthreads();

        // ---- S = Q @ K^T (128x64), warp = 16 rows x 64 cols ----
        float s[8][4];
        #pragma unroll
        for (int i = 0; i < 8; i++)
            #pragma unroll
            for (int j = 0; j < 4; j++) s[i][j] = 0.f;

        #pragma unroll
        for (int ks = 0; ks < 4; ks++) {
            uint32_t ah[4], al[4];
            LDMX4(ah, a_addr(smb + AT_QH, m0s, ks*32, lane, AT_STRIDE));
            LDMX4(al, a_addr(smb + AT_QL, m0s, ks*32, lane, AT_STRIDE));
            #pragma unroll
            for (int nt = 0; nt < 8; nt++) {
                uint32_t bh[2], bl[2];
                LDMX2(bh, b_addr(smb + AT_KH, nt*8, ks*32, lane, AT_STRIDE));
                LDMX2(bl, b_addr(smb + AT_KL, nt*8, ks*32, lane, AT_STRIDE));
                MMA3(s[nt], ah, al, bh, bl);
            }
        }

        // ---- mask + exp + split-store P ----
        {
            const int qr0 = q0 + m0s + g;
            const int qr1 = qr0 + 8;
            #pragma unroll
            for (int nt = 0; nt < 8; nt++) {
                const int kc = kt*64 + nt*8 + 2*t;
                float p00 = (kc     <= qr0) ? __expf(s[nt][0]*0.125f - mA) : 0.f;
                float p01 = (kc + 1 <= qr0) ? __expf(s[nt][1]*0.125f - mA) : 0.f;
                float p10 = (kc     <= qr1) ? __expf(s[nt][2]*0.125f - mB) : 0.f;
                float p11 = (kc + 1 <= qr1) ? __expf(s[nt][3]*0.125f - mB) : 0.f;
                __nv_bfloat16 h00 = __float2bfloat16_rn(p00);
                __nv_bfloat16 h01 = __float2bfloat16_rn(p01);
                __nv_bfloat16 h10 = __float2bfloat16_rn(p10);
                __nv_bfloat16 h11 = __float2bfloat16_rn(p11);
                __nv_bfloat16 l00 = __float2bfloat16_rn(p00 - __bfloat162float(h00));
                __nv_bfloat16 l01 = __float2bfloat16_rn(p01 - __bfloat162float(h01));
                __nv_bfloat16 l10 = __float2bfloat16_rn(p10 - __bfloat162float(h10));
                __nv_bfloat16 l11 = __float2bfloat16_rn(p11 - __bfloat162float(h11));
                const int cb = (nt*8 + 2*t) * 2;
                *(uint32_t*)(sm + AT_PH + (m0s+g)*AT_STRIDE   + cb) = bpack(h00, h01);
                *(uint32_t*)(sm + AT_PH + (m0s+8+g)*AT_STRIDE + cb) = bpack(h10, h11);
                *(uint32_t*)(sm + AT_PL + (m0s+g)*AT_STRIDE   + cb) = bpack(l00, l01);
                *(uint32_t*)(sm + AT_PL + (m0s+8+g)*AT_STRIDE + cb) = bpack(l10, l11);
            }
        }
        __syncthreads();

        // ---- O += P @ Vt^T, warp = 32 rows x 64 cols ----
        #pragma unroll
        for (int ks = 0; ks < 4; ks++) {
            uint32_t pah[2][4], pal[2][4];
            #pragma unroll
            for (int mt = 0; mt < 2; mt++) {
                LDMX4(pah[mt], a_addr(smb + AT_PH, m0p + mt*16, ks*32, lane, AT_STRIDE));
                LDMX4(pal[mt], a_addr(smb + AT_PL, m0p + mt*16, ks*32, lane, AT_STRIDE));
            }
            #pragma unroll
            for (int nt = 0; nt < 8; nt++) {
                uint32_t bh[2], bl[2];
                LDMX2(bh, b_addr(smb + AT_VTH, n0p + nt*8, ks*32, lane, AT_STRIDE));
                LDMX2(bl, b_addr(smb + AT_VTL, n0p + nt*8, ks*32, lane, AT_STRIDE));
                #pragma unroll
                for (int mt = 0; mt < 2; mt++)
                    MMA3(o[mt*8 + nt], pah[mt], pal[mt], bh, bl);
            }
        }
        __syncthreads();
    }

    // ---- normalize + store ----
    #pragma unroll
    for (int mt = 0; mt < 2; mt++) {
        const int r0 = m0p + mt*16 + g;
        const float i0 = smf[AT_RIL/4 + r0];
        const float i1 = smf[AT_RIL/4 + r0 + 8];
        #pragma unroll
        for (int nt = 0; nt < 8; nt++) {
            const int c = d0 + n0p + nt*8 + 2*t;
            float2 v0 = make_float2(o[mt*8+nt][0]*i0, o[mt*8+nt][1]*i0);
            float2 v1 = make_float2(o[mt*8+nt][2]*i1, o[mt*8+nt][3]*i1);
            *(float2*)(out + (size_t)(b*SEQ + q0 + r0)     * EMB + c) = v0;
            *(float2*)(out + (size_t)(b*SEQ + q0 + r0 + 8) * EMB + c) = v1;
        }
    }
}

// ===========================================================================
extern "C" void kernel_launch(void* const* d_in, const int* in_sizes, int n_in,
                              void* d_out, int out_size)
{
    const float* x  = (const float*)d_in[0];
    const float* Wk = (const float*)d_in[1];
    const float* Wq = (const float*)d_in[2];
    const float* Wv = (const float*)d_in[3];
    float* out = (float*)d_out;

    float *Kp, *Qp, *Vp, *Mp, *Lp;
    cudaGetSymbolAddress((void**)&Kp, g_K);
    cudaGetSymbolAddress((void**)&Qp, g_Q);
    cudaGetSymbolAddress((void**)&Vp, g_V);
    cudaGetSymbolAddress((void**)&Mp, g_M);
    cudaGetSymbolAddress((void**)&Lp, g_L);

    cudaFuncSetAttribute(qkproj_mma, cudaFuncAttributeMaxDynamicSharedMemorySize, PJ_SMEM);
    cudaFuncSetAttribute(vproj_mma,  cudaFuncAttributeMaxDynamicSharedMemorySize, PJ_SMEM);
    cudaFuncSetAttribute(attn_mma,   cudaFuncAttributeMaxDynamicSharedMemorySize, AT_SMEM);

    // Q,K projections (tensor, bf16x3)
    qkproj_mma<<<dim3(1, BT/128), 256, PJ_SMEM>>>(x, Wk, Wq, Kp, Qp);

    // V projection (tensor, bf16x3)
    vproj_mma<<<dim3(EMB/128, BT/128), 256, PJ_SMEM>>>(x, Wv, Vp);

    // Softmax stats (fp32, exact)
    attn_stats<<<BT/64, 256>>>(Qp, Kp, Mp, Lp);

    // Attention output (tensor, bf16x3)
    attn_mma<<<dim3(EMB/128, SEQ/128, BATCH), 256, AT_SMEM>>>(
        Qp, Kp, Vp, Mp, Lp, out);
}

// round 5
// speedup vs baseline: 1.7633x; 1.0066x over previous
#include <cuda_runtime.h>
#include <cuda_bf16.h>
#include <cstdint>

#define HEADSZ 64
#define EMB    1024
#define BATCH  4
#define SEQ    4096
#define BT     (BATCH*SEQ)

// Scratch (allocation-free)
__device__ float g_K[(size_t)BT*HEADSZ];
__device__ float g_Q[(size_t)BT*HEADSZ];
__device__ float g_V[(size_t)BT*EMB];
__device__ float g_M[BT];
__device__ float g_L[BT];

// ===========================================================================
// helpers
// ===========================================================================
__device__ __forceinline__ uint32_t smem_u32(const void* p) {
    uint32_t a;
    asm("{ .reg .u64 t; cvta.to.shared.u64 t, %1; cvt.u32.u64 %0, t; }"
        : "=r"(a) : "l"(p));
    return a;
}

#define LDMX4(r, a) \
    asm volatile("ldmatrix.sync.aligned.m8n8.x4.shared.b16 {%0,%1,%2,%3}, [%4];" \
        : "=r"((r)[0]), "=r"((r)[1]), "=r"((r)[2]), "=r"((r)[3]) : "r"(a))
#define LDMX2(r, a) \
    asm volatile("ldmatrix.sync.aligned.m8n8.x2.shared.b16 {%0,%1}, [%2];" \
        : "=r"((r)[0]), "=r"((r)[1]) : "r"(a))

#define MMA_BF16(d, a, b) \
    asm volatile("mma.sync.aligned.m16n8k16.row.col.f32.bf16.bf16.f32 " \
        "{%0,%1,%2,%3}, {%4,%5,%6,%7}, {%8,%9}, {%0,%1,%2,%3};" \
        : "+f"((d)[0]), "+f"((d)[1]), "+f"((d)[2]), "+f"((d)[3]) \
        : "r"((a)[0]), "r"((a)[1]), "r"((a)[2]), "r"((a)[3]), \
          "r"((b)[0]), "r"((b)[1]))

#define MMA3(d, ah, al, bh, bl) do { \
    MMA_BF16(d, ah, bh); MMA_BF16(d, ah, bl); MMA_BF16(d, al, bh); } while (0)

// A-fragment ldmatrix address (m16 x k16, [row][k] layout, strideB bytes/row)
__device__ __forceinline__ uint32_t a_addr(uint32_t base, int row, int kbyte,
                                           int lane, int strideB) {
    return base + (uint32_t)(row + (lane & 15)) * strideB + kbyte +
           ((lane >> 4) << 4);
}
// B-fragment ldmatrix address (k16 x n8, [n][k] layout)
__device__ __forceinline__ uint32_t b_addr(uint32_t base, int row, int kbyte,
                                           int lane, int strideB) {
    return base + (uint32_t)(row + (lane & 7)) * strideB + kbyte +
           (((lane >> 3) & 1) << 4);
}

__device__ __forceinline__ uint32_t bpack(__nv_bfloat16 a, __nv_bfloat16 b) {
    return ((uint32_t)__bfloat16_as_ushort(b) << 16) |
           (uint32_t)__bfloat16_as_ushort(a);
}

// Split a float4 (4 consecutive k-elements) into hi/lo bf16 pairs; store 8B each.
__device__ __forceinline__ void split_store4(float4 v, char* ph, char* pl) {
    __nv_bfloat16 hx = __float2bfloat16_rn(v.x), hy = __float2bfloat16_rn(v.y);
    __nv_bfloat16 hz = __float2bfloat16_rn(v.z), hw = __float2bfloat16_rn(v.w);
    __nv_bfloat16 lx = __float2bfloat16_rn(v.x - __bfloat162float(hx));
    __nv_bfloat16 ly = __float2bfloat16_rn(v.y - __bfloat162float(hy));
    __nv_bfloat16 lz = __float2bfloat16_rn(v.z - __bfloat162float(hz));
    __nv_bfloat16 lw = __float2bfloat16_rn(v.w - __bfloat162float(hw));
    uint2 h; h.x = bpack(hx, hy); h.y = bpack(hz, hw);
    uint2 l; l.x = bpack(lx, ly); l.y = bpack(lz, lw);
    *(uint2*)ph = h;
    *(uint2*)pl = l;
}

// ===========================================================================
// Fused Q/K projection: g_K = x@Wk^T, g_Q = x@Wq^T  (bf16x3 mma)
// CTA tile 128 rows x 128 cols (cols 0-63 -> K, 64-127 -> Q). BK=32.
// ===========================================================================
#define PJ_STRIDE 80            // bytes per row (40 bf16)
#define PJ_AH 0
#define PJ_AL 10240
#define PJ_BH 20480
#define PJ_BL 30720
#define PJ_SMEM 40960

__global__ __launch_bounds__(256, 1) void qkproj_mma(
    const float* __restrict__ A, const float* __restrict__ Wk,
    const float* __restrict__ Wq, float* __restrict__ Ck,
    float* __restrict__ Cq)
{
    extern __shared__ char sm[];
    const uint32_t smb = smem_u32(sm);
    const int tid = threadIdx.x, wid = tid >> 5, lane = tid & 31;
    const int g = lane >> 2, t = lane & 3;
    const int row0 = blockIdx.y * 128;
    const int m0 = (wid & 3) * 32, n0 = (wid >> 2) * 64;

    float o[16][4];
    #pragma unroll
    for (int i = 0; i < 16; i++)
        #pragma unroll
        for (int j = 0; j < 4; j++) o[i][j] = 0.f;

    const int lr = tid >> 1, lc0 = (tid & 1) * 16;
    const float* arow = A + (size_t)(row0 + lr) * EMB + lc0;
    const float* brow = (lr < 64 ? Wk + (size_t)lr * EMB
                                 : Wq + (size_t)(lr - 64) * EMB) + lc0;

    for (int kc = 0; kc < EMB / 32; kc++) {
        #pragma unroll
        for (int j = 0; j < 4; j++) {
            float4 va = *(const float4*)(arow + kc * 32 + j * 4);
            split_store4(va, sm + PJ_AH + lr * PJ_STRIDE + lc0 * 2 + j * 8,
                             sm + PJ_AL + lr * PJ_STRIDE + lc0 * 2 + j * 8);
            float4 vb = *(const float4*)(brow + kc * 32 + j * 4);
            split_store4(vb, sm + PJ_BH + lr * PJ_STRIDE + lc0 * 2 + j * 8,
                             sm + PJ_BL + lr * PJ_STRIDE + lc0 * 2 + j * 8);
        }
        __syncthreads();
        #pragma unroll
        for (int ks = 0; ks < 2; ks++) {
            uint32_t ah[2][4], al[2][4];
            #pragma unroll
            for (int mt = 0; mt < 2; mt++) {
                LDMX4(ah[mt], a_addr(smb + PJ_AH, m0 + mt*16, ks*32, lane, PJ_STRIDE));
                LDMX4(al[mt], a_addr(smb + PJ_AL, m0 + mt*16, ks*32, lane, PJ_STRIDE));
            }
            #pragma unroll
            for (int nt = 0; nt < 8; nt++) {
                uint32_t bh[2], bl[2];
                LDMX2(bh, b_addr(smb + PJ_BH, n0 + nt*8, ks*32, lane, PJ_STRIDE));
                LDMX2(bl, b_addr(smb + PJ_BL, n0 + nt*8, ks*32, lane, PJ_STRIDE));
                #pragma unroll
                for (int mt = 0; mt < 2; mt++)
                    MMA3(o[mt*8 + nt], ah[mt], al[mt], bh, bl);
            }
        }
        __syncthreads();
    }

    float* Cp = (n0 == 0) ? Ck : Cq;
    #pragma unroll
    for (int mt = 0; mt < 2; mt++)
        #pragma unroll
        for (int nt = 0; nt < 8; nt++) {
            const int r0 = row0 + m0 + mt*16 + g;
            const int c  = nt*8 + 2*t;
            float2 v0 = make_float2(o[mt*8+nt][0], o[mt*8+nt][1]);
            float2 v1 = make_float2(o[mt*8+nt][2], o[mt*8+nt][3]);
            *(float2*)(Cp + (size_t)r0 * HEADSZ + c)       = v0;
            *(float2*)(Cp + (size_t)(r0 + 8) * HEADSZ + c) = v1;
        }
}

// ===========================================================================
// V projection: g_V = x@Wv^T  (bf16x3 mma), tile 128x128, BK=32
// ===========================================================================
__global__ __launch_bounds__(256, 1) void vproj_mma(
    const float* __restrict__ A, const float* __restrict__ W,
    float* __restrict__ C)
{
    extern __shared__ char sm[];
    const uint32_t smb = smem_u32(sm);
    const int tid = threadIdx.x, wid = tid >> 5, lane = tid & 31;
    const int g = lane >> 2, t = lane & 3;
    const int row0 = blockIdx.y * 128;
    const int col0 = blockIdx.x * 128;
    const int m0 = (wid & 3) * 32, n0 = (wid >> 2) * 64;

    float o[16][4];
    #pragma unroll
    for (int i = 0; i < 16; i++)
        #pragma unroll
        for (int j = 0; j < 4; j++) o[i][j] = 0.f;

    const int lr = tid >> 1, lc0 = (tid & 1) * 16;
    const float* arow = A + (size_t)(row0 + lr) * EMB + lc0;
    const float* brow = W + (size_t)(col0 + lr) * EMB + lc0;

    for (int kc = 0; kc < EMB / 32; kc++) {
        #pragma unroll
        for (int j = 0; j < 4; j++) {
            float4 va = *(const float4*)(arow + kc * 32 + j * 4);
            split_store4(va, sm + PJ_AH + lr * PJ_STRIDE + lc0 * 2 + j * 8,
                             sm + PJ_AL + lr * PJ_STRIDE + lc0 * 2 + j * 8);
            float4 vb = *(const float4*)(brow + kc * 32 + j * 4);
            split_store4(vb, sm + PJ_BH + lr * PJ_STRIDE + lc0 * 2 + j * 8,
                             sm + PJ_BL + lr * PJ_STRIDE + lc0 * 2 + j * 8);
        }
        __syncthreads();
        #pragma unroll
        for (int ks = 0; ks < 2; ks++) {
            uint32_t ah[2][4], al[2][4];
            #pragma unroll
            for (int mt = 0; mt < 2; mt++) {
                LDMX4(ah[mt], a_addr(smb + PJ_AH, m0 + mt*16, ks*32, lane, PJ_STRIDE));
                LDMX4(al[mt], a_addr(smb + PJ_AL, m0 + mt*16, ks*32, lane, PJ_STRIDE));
            }
            #pragma unroll
            for (int nt = 0; nt < 8; nt++) {
                uint32_t bh[2], bl[2];
                LDMX2(bh, b_addr(smb + PJ_BH, n0 + nt*8, ks*32, lane, PJ_STRIDE));
                LDMX2(bl, b_addr(smb + PJ_BL, n0 + nt*8, ks*32, lane, PJ_STRIDE));
                #pragma unroll
                for (int mt = 0; mt < 2; mt++)
                    MMA3(o[mt*8 + nt], ah[mt], al[mt], bh, bl);
            }
        }
        __syncthreads();
    }

    #pragma unroll
    for (int mt = 0; mt < 2; mt++)
        #pragma unroll
        for (int nt = 0; nt < 8; nt++) {
            const int r0 = row0 + m0 + mt*16 + g;
            const int c  = col0 + n0 + nt*8 + 2*t;
            float2 v0 = make_float2(o[mt*8+nt][0], o[mt*8+nt][1]);
            float2 v1 = make_float2(o[mt*8+nt][2], o[mt*8+nt][3]);
            *(float2*)(C + (size_t)r0 * EMB + c)       = v0;
            *(float2*)(C + (size_t)(r0 + 8) * EMB + c) = v1;
        }
}

// ===========================================================================
// Pass A: per-row softmax stats (fp32, exact) — unchanged
// ===========================================================================
__global__ __launch_bounds__(256) void attn_stats(
    const float* __restrict__ Qb, const float* __restrict__ Kb,
    float* __restrict__ Mo, float* __restrict__ Lo)
{
    __shared__ float Qs[64][HEADSZ+1];
    __shared__ float Ks[64][HEADSZ+1];
    __shared__ float rm[64], rl[64];

    const int tid = threadIdx.x, tx = tid & 15, ty = tid >> 4;
    const int nq = SEQ/64;
    const int b  = blockIdx.x / nq;
    const int q0 = (nq - 1 - (blockIdx.x % nq)) * 64;
    const float* Qbase = Qb + (size_t)(b*SEQ + q0) * HEADSZ;
    const float* Kbase = Kb + (size_t)b * SEQ * HEADSZ;

    #pragma unroll
    for (int i = tid; i < 64*HEADSZ; i += 256)
        Qs[i>>6][i&63] = Qbase[i];
    if (tid < 64) { rm[tid] = -1e30f; rl[tid] = 0.f; }
    __syncthreads();

    const int nkt = q0/64 + 1;
    for (int kt = 0; kt < nkt; kt++) {
        #pragma unroll
        for (int i = tid; i < 64*HEADSZ; i += 256)
            Ks[i>>6][i&63] = Kbase[(size_t)kt*64*HEADSZ + i];
        __syncthreads();

        float s[4][4];
        #pragma unroll
        for (int u = 0; u < 4; u++)
            #pragma unroll
            for (int v = 0; v < 4; v++) s[u][v] = 0.f;

        #pragma unroll 8
        for (int d = 0; d < HEADSZ; d++) {
            float a[4], bb[4];
            #pragma unroll
            for (int u = 0; u < 4; u++) a[u] = Qs[ty*4+u][d];
            #pragma unroll
            for (int v = 0; v < 4; v++) bb[v] = Ks[tx*4+v][d];
            #pragma unroll
            for (int u = 0; u < 4; u++)
                #pragma unroll
                for (int v = 0; v < 4; v++)
                    s[u][v] = fmaf(a[u], bb[v], s[u][v]);
        }

        const bool diag = (kt == nkt - 1);
        #pragma unroll
        for (int u = 0; u < 4; u++) {
            const int qi = q0 + ty*4 + u;
            #pragma unroll
            for (int v = 0; v < 4; v++) {
                const int kj = kt*64 + tx*4 + v;
                s[u][v] *= 0.125f;
                if (diag && kj > qi) s[u][v] = -1e30f;
            }
        }

        float newm[4], ps[4];
        #pragma unroll
        for (int u = 0; u < 4; u++) {
            float tm = fmaxf(fmaxf(s[u][0], s[u][1]), fmaxf(s[u][2], s[u][3]));
            for (int off = 8; off; off >>= 1)
                tm = fmaxf(tm, __shfl_xor_sync(0xffffffffu, tm, off));
            newm[u] = fmaxf(rm[ty*4+u], tm);
            float p = 0.f;
            #pragma unroll
            for (int v = 0; v < 4; v++) p += __expf(s[u][v] - newm[u]);
            for (int off = 8; off; off >>= 1)
                p += __shfl_xor_sync(0xffffffffu, p, off);
            ps[u] = p;
        }
        if (tx == 0) {
            #pragma unroll
            for (int u = 0; u < 4; u++) {
                const int r = ty*4 + u;
                rl[r] = rl[r] * __expf(rm[r] - newm[u]) + ps[u];
                rm[r] = newm[u];
            }
        }
        __syncthreads();
    }
    if (tid < 64) {
        Mo[(size_t)b*SEQ + q0 + tid] = rm[tid];
        Lo[(size_t)b*SEQ + q0 + tid] = rl[tid];
    }
}

// ===========================================================================
// Pass B on mma.sync (bf16x3). Per CTA: 128 queries x 128 output dims.
// Per 64-key tile: S = Q@K^T (mma) -> exp/mask (regs, precomputed m)
//                  -> P split to smem -> O += P@Vt^T (mma).
// ===========================================================================
#define AT_STRIDE 144          // bytes per operand row (72 bf16)
#define AT_RM   0
#define AT_RIL  512
#define AT_QH   1024
#define AT_QL   (AT_QH  + 128*AT_STRIDE)   // 19456
#define AT_KH   (AT_QL  + 128*AT_STRIDE)   // 37888
#define AT_KL   (AT_KH  +  64*AT_STRIDE)   // 47104
#define AT_VTH  (AT_KL  +  64*AT_STRIDE)   // 56320
#define AT_VTL  (AT_VTH + 128*AT_STRIDE)   // 74752
#define AT_PH   (AT_VTL + 128*AT_STRIDE)   // 93184
#define AT_PL   (AT_PH  + 128*AT_STRIDE)   // 111616
#define AT_SMEM (AT_PL  + 128*AT_STRIDE)   // 130048

__global__ __launch_bounds__(256, 1) void attn_mma(
    const float* __restrict__ Qb, const float* __restrict__ Kb,
    const float* __restrict__ Vb, const float* __restrict__ Mo,
    const float* __restrict__ Lo, float* __restrict__ out)
{
    extern __shared__ char sm[];
    const uint32_t smb = smem_u32(sm);
    float* smf = (float*)sm;
    const int tid = threadIdx.x, wid = tid >> 5, lane = tid & 31;
    const int g = lane >> 2, t = lane & 3;
    const int b  = blockIdx.z;
    const int qt = (SEQ/128 - 1) - blockIdx.y;
    const int q0 = qt * 128;
    const int d0 = blockIdx.x * 128;

    const float* Qbase = Qb + (size_t)(b*SEQ + q0) * HEADSZ;
    const float* Kbase = Kb + (size_t)b * SEQ * HEADSZ;
    const float* Vbase = Vb + (size_t)b * SEQ * EMB + d0;

    if (tid < 128) {
        smf[AT_RM/4  + tid] = Mo[(size_t)b*SEQ + q0 + tid];
        smf[AT_RIL/4 + tid] = 1.0f / Lo[(size_t)b*SEQ + q0 + tid];
    }
    // Q tile 128x64 -> split bf16
    {
        const int r = tid >> 1, c0 = (tid & 1) * 32;
        const float* qr = Qbase + (size_t)r * HEADSZ + c0;
        #pragma unroll
        for (int j = 0; j < 8; j++) {
            float4 v = *(const float4*)(qr + j*4);
            split_store4(v, sm + AT_QH + r*AT_STRIDE + c0*2 + j*8,
                            sm + AT_QL + r*AT_STRIDE + c0*2 + j*8);
        }
    }
    __syncthreads();

    // hoisted row constants
    const int m0s = wid * 16;                       // S-phase rows
    const float mA = smf[AT_RM/4 + m0s + g];
    const float mB = smf[AT_RM/4 + m0s + 8 + g];
    const int m0p = (wid & 3) * 32;                 // PV-phase rows
    const int n0p = (wid >> 2) * 64;                // PV-phase cols

    float o[16][4];
    #pragma unroll
    for (int i = 0; i < 16; i++)
        #pragma unroll
        for (int j = 0; j < 4; j++) o[i][j] = 0.f;

    const int nkt = 2*qt + 2;
    for (int kt = 0; kt < nkt; kt++) {
        // K tile 64x64 -> split
        {
            const int r = tid >> 2, c0 = (tid & 3) * 16;
            const float* kr = Kbase + (size_t)(kt*64 + r) * HEADSZ + c0;
            #pragma unroll
            for (int j = 0; j < 4; j++) {
                float4 v = *(const float4*)(kr + j*4);
                split_store4(v, sm + AT_KH + r*AT_STRIDE + c0*2 + j*8,
                                sm + AT_KL + r*AT_STRIDE + c0*2 + j*8);
            }
        }
        // V tile 64x128 -> transpose -> Vt[dim][key] split
        {
            const float* v0 = Vbase + (size_t)(kt*64 + 2*lane) * EMB + wid*16;
            const float* v1 = v0 + EMB;
            #pragma unroll
            for (int j = 0; j < 4; j++) {
                float4 a = *(const float4*)(v0 + j*4);
                float4 c = *(const float4*)(v1 + j*4);
                const float pa[4] = {a.x, a.y, a.z, a.w};
                const float pc[4] = {c.x, c.y, c.z, c.w};
                #pragma unroll
                for (int e = 0; e < 4; e++) {
                    const int dim = wid*16 + j*4 + e;
                    __nv_bfloat16 h0 = __float2bfloat16_rn(pa[e]);
                    __nv_bfloat16 h1 = __float2bfloat16_rn(pc[e]);
                    __nv_bfloat16 l0 = __float2bfloat16_rn(pa[e] - __bfloat162float(h0));
                    __nv_bfloat16 l1 = __float2bfloat16_rn(pc[e] - __bfloat162float(h1));
                    *(uint32_t*)(sm + AT_VTH + dim*AT_STRIDE + lane*4) = bpack(h0, h1);
                    *(uint32_t*)(sm + AT_VTL + dim*AT_STRIDE + lane*4) = bpack(l0, l1);
                }
            }
        }
        __syncthreads();

        // ---- S = Q @ K^T (128x64), warp = 16 rows x 64 cols ----
        float s[8][4];
        #pragma unroll
        for (int i = 0; i < 8; i++)
            #pragma unroll
            for (int j = 0; j < 4; j++) s[i][j] = 0.f;

        #pragma unroll
        for (int ks = 0; ks < 4; ks++) {
            uint32_t ah[4], al[4];
            LDMX4(ah, a_addr(smb + AT_QH, m0s, ks*32, lane, AT_STRIDE));
            LDMX4(al, a_addr(smb + AT_QL, m0s, ks*32, lane, AT_STRIDE));
            #pragma unroll
            for (int nt = 0; nt < 8; nt++) {
                uint32_t bh[2], bl[2];
                LDMX2(bh, b_addr(smb + AT_KH, nt*8, ks*32, lane, AT_STRIDE));
                LDMX2(bl, b_addr(smb + AT_KL, nt*8, ks*32, lane, AT_STRIDE));
                MMA3(s[nt], ah, al, bh, bl);
            }
        }

        // ---- mask + exp + split-store P ----
        {
            const int qr0 = q0 + m0s + g;
            const int qr1 = qr0 + 8;
            #pragma unroll
            for (int nt = 0; nt < 8; nt++) {
                const int kc = kt*64 + nt*8 + 2*t;
                float p00 = (kc     <= qr0) ? __expf(s[nt][0]*0.125f - mA) : 0.f;
                float p01 = (kc + 1 <= qr0) ? __expf(s[nt][1]*0.125f - mA) : 0.f;
                float p10 = (kc     <= qr1) ? __expf(s[nt][2]*0.125f - mB) : 0.f;
                float p11 = (kc + 1 <= qr1) ? __expf(s[nt][3]*0.125f - mB) : 0.f;
                __nv_bfloat16 h00 = __float2bfloat16_rn(p00);
                __nv_bfloat16 h01 = __float2bfloat16_rn(p01);
                __nv_bfloat16 h10 = __float2bfloat16_rn(p10);
                __nv_bfloat16 h11 = __float2bfloat16_rn(p11);
                __nv_bfloat16 l00 = __float2bfloat16_rn(p00 - __bfloat162float(h00));
                __nv_bfloat16 l01 = __float2bfloat16_rn(p01 - __bfloat162float(h01));
                __nv_bfloat16 l10 = __float2bfloat16_rn(p10 - __bfloat162float(h10));
                __nv_bfloat16 l11 = __float2bfloat16_rn(p11 - __bfloat162float(h11));
                const int cb = (nt*8 + 2*t) * 2;
                *(uint32_t*)(sm + AT_PH + (m0s+g)*AT_STRIDE   + cb) = bpack(h00, h01);
                *(uint32_t*)(sm + AT_PH + (m0s+8+g)*AT_STRIDE + cb) = bpack(h10, h11);
                *(uint32_t*)(sm + AT_PL + (m0s+g)*AT_STRIDE   + cb) = bpack(l00, l01);
                *(uint32_t*)(sm + AT_PL + (m0s+8+g)*AT_STRIDE + cb) = bpack(l10, l11);
            }
        }
        __syncthreads();

        // ---- O += P @ Vt^T, warp = 32 rows x 64 cols ----
        #pragma unroll
        for (int ks = 0; ks < 4; ks++) {
            uint32_t pah[2][4], pal[2][4];
            #pragma unroll
            for (int mt = 0; mt < 2; mt++) {
                LDMX4(pah[mt], a_addr(smb + AT_PH, m0p + mt*16, ks*32, lane, AT_STRIDE));
                LDMX4(pal[mt], a_addr(smb + AT_PL, m0p + mt*16, ks*32, lane, AT_STRIDE));
            }
            #pragma unroll
            for (int nt = 0; nt < 8; nt++) {
                uint32_t bh[2], bl[2];
                LDMX2(bh, b_addr(smb + AT_VTH, n0p + nt*8, ks*32, lane, AT_STRIDE));
                LDMX2(bl, b_addr(smb + AT_VTL, n0p + nt*8, ks*32, lane, AT_STRIDE));
                #pragma unroll
                for (int mt = 0; mt < 2; mt++)
                    MMA3(o[mt*8 + nt], pah[mt], pal[mt], bh, bl);
            }
        }
        __syncthreads();
    }

    // ---- normalize + store ----
    #pragma unroll
    for (int mt = 0; mt < 2; mt++) {
        const int r0 = m0p + mt*16 + g;
        const float i0 = smf[AT_RIL/4 + r0];
        const float i1 = smf[AT_RIL/4 + r0 + 8];
        #pragma unroll
        for (int nt = 0; nt < 8; nt++) {
            const int c = d0 + n0p + nt*8 + 2*t;
            float2 v0 = make_float2(o[mt*8+nt][0]*i0, o[mt*8+nt][1]*i0);
            float2 v1 = make_float2(o[mt*8+nt][2]*i1, o[mt*8+nt][3]*i1);
            *(float2*)(out + (size_t)(b*SEQ + q0 + r0)     * EMB + c) = v0;
            *(float2*)(out + (size_t)(b*SEQ + q0 + r0 + 8) * EMB + c) = v1;
        }
    }
}

// ===========================================================================
extern "C" void kernel_launch(void* const* d_in, const int* in_sizes, int n_in,
                              void* d_out, int out_size)
{
    const float* x  = (const float*)d_in[0];
    const float* Wk = (const float*)d_in[1];
    const float* Wq = (const float*)d_in[2];
    const float* Wv = (const float*)d_in[3];
    float* out = (float*)d_out;

    float *Kp, *Qp, *Vp, *Mp, *Lp;
    cudaGetSymbolAddress((void**)&Kp, g_K);
    cudaGetSymbolAddress((void**)&Qp, g_Q);
    cudaGetSymbolAddress((void**)&Vp, g_V);
    cudaGetSymbolAddress((void**)&Mp, g_M);
    cudaGetSymbolAddress((void**)&Lp, g_L);

    cudaFuncSetAttribute(qkproj_mma, cudaFuncAttributeMaxDynamicSharedMemorySize, PJ_SMEM);
    cudaFuncSetAttribute(vproj_mma,  cudaFuncAttributeMaxDynamicSharedMemorySize, PJ_SMEM);
    cudaFuncSetAttribute(attn_mma,   cudaFuncAttributeMaxDynamicSharedMemorySize, AT_SMEM);

    // Q,K projections (tensor, bf16x3)
    qkproj_mma<<<dim3(1, BT/128), 256, PJ_SMEM>>>(x, Wk, Wq, Kp, Qp);

    // V projection (tensor, bf16x3)
    vproj_mma<<<dim3(EMB/128, BT/128), 256, PJ_SMEM>>>(x, Wv, Vp);

    // Softmax stats (fp32, exact)
    attn_stats<<<BT/64, 256>>>(Qp, Kp, Mp, Lp);

    // Attention output (tensor, bf16x3)
    attn_mma<<<dim3(EMB/128, SEQ/128, BATCH), 256, AT_SMEM>>>(
        Qp, Kp, Vp, Mp, Lp, out);
}

// round 6
// speedup vs baseline: 2.4624x; 1.3965x over previous
#include <cuda_runtime.h>
#include <cuda_bf16.h>
#include <cstdint>

#define HEADSZ 64
#define EMB    1024
#define BATCH  4
#define SEQ    4096
#define BT     (BATCH*SEQ)

// Scratch (allocation-free): split bf16 hi/lo projections
__device__ __nv_bfloat16 g_Qh[(size_t)BT*HEADSZ];
__device__ __nv_bfloat16 g_Ql[(size_t)BT*HEADSZ];
__device__ __nv_bfloat16 g_Kh[(size_t)BT*HEADSZ];
__device__ __nv_bfloat16 g_Kl[(size_t)BT*HEADSZ];
__device__ __nv_bfloat16 g_Vh[(size_t)BT*EMB];
__device__ __nv_bfloat16 g_Vl[(size_t)BT*EMB];

// ===========================================================================
// helpers
// ===========================================================================
__device__ __forceinline__ uint32_t smem_u32(const void* p) {
    uint32_t a;
    asm("{ .reg .u64 t; cvta.to.shared.u64 t, %1; cvt.u32.u64 %0, t; }"
        : "=r"(a) : "l"(p));
    return a;
}

#define LDMX4(r, a) \
    asm volatile("ldmatrix.sync.aligned.m8n8.x4.shared.b16 {%0,%1,%2,%3}, [%4];" \
        : "=r"((r)[0]), "=r"((r)[1]), "=r"((r)[2]), "=r"((r)[3]) : "r"(a))
#define LDMX2(r, a) \
    asm volatile("ldmatrix.sync.aligned.m8n8.x2.shared.b16 {%0,%1}, [%2];" \
        : "=r"((r)[0]), "=r"((r)[1]) : "r"(a))
#define LDMX2T(r, a) \
    asm volatile("ldmatrix.sync.aligned.m8n8.x2.trans.shared.b16 {%0,%1}, [%2];" \
        : "=r"((r)[0]), "=r"((r)[1]) : "r"(a))

#define MMA_BF16(d, a, b) \
    asm volatile("mma.sync.aligned.m16n8k16.row.col.f32.bf16.bf16.f32 " \
        "{%0,%1,%2,%3}, {%4,%5,%6,%7}, {%8,%9}, {%0,%1,%2,%3};" \
        : "+f"((d)[0]), "+f"((d)[1]), "+f"((d)[2]), "+f"((d)[3]) \
        : "r"((a)[0]), "r"((a)[1]), "r"((a)[2]), "r"((a)[3]), \
          "r"((b)[0]), "r"((b)[1]))

#define MMA3(d, ah, al, bh, bl) do { \
    MMA_BF16(d, ah, bh); MMA_BF16(d, ah, bl); MMA_BF16(d, al, bh); } while (0)

#define CPA16(dst, src) \
    asm volatile("cp.async.cg.shared.global [%0], [%1], 16;" :: "r"(dst), "l"(src))
#define CPA_COMMIT() asm volatile("cp.async.commit_group;" ::: "memory")
#define CPA_WAIT(n)  asm volatile("cp.async.wait_group %0;" :: "n"(n) : "memory")

// A-fragment ldmatrix address (m16 x k16, [row][k] layout, strideB bytes/row)
__device__ __forceinline__ uint32_t a_addr(uint32_t base, int row, int kbyte,
                                           int lane, int strideB) {
    return base + (uint32_t)(row + (lane & 15)) * strideB + kbyte +
           ((lane >> 4) << 4);
}
// B-fragment ldmatrix address (k16 x n8, [n][k] layout)
__device__ __forceinline__ uint32_t b_addr(uint32_t base, int row, int kbyte,
                                           int lane, int strideB) {
    return base + (uint32_t)(row + (lane & 7)) * strideB + kbyte +
           (((lane >> 3) & 1) << 4);
}

__device__ __forceinline__ uint32_t bpack(__nv_bfloat16 a, __nv_bfloat16 b) {
    return ((uint32_t)__bfloat16_as_ushort(b) << 16) |
           (uint32_t)__bfloat16_as_ushort(a);
}

// pack (a,b) hi pair, return it, write lo pair
__device__ __forceinline__ uint32_t packsplit2(float a, float b, uint32_t& lo) {
    __nv_bfloat16 ha = __float2bfloat16_rn(a), hb = __float2bfloat16_rn(b);
    lo = bpack(__float2bfloat16_rn(a - __bfloat162float(ha)),
               __float2bfloat16_rn(b - __bfloat162float(hb)));
    return bpack(ha, hb);
}

// Split a float4 into hi/lo bf16 pairs; store 8B each.
__device__ __forceinline__ void split_store4(float4 v, char* ph, char* pl) {
    uint32_t l0, l1;
    uint32_t h0 = packsplit2(v.x, v.y, l0);
    uint32_t h1 = packsplit2(v.z, v.w, l1);
    uint2 h; h.x = h0; h.y = h1;
    uint2 l; l.x = l0; l.y = l1;
    *(uint2*)ph = h;
    *(uint2*)pl = l;
}

// ===========================================================================
// Fused Q/K projection (bf16x3 mma), outputs split bf16 hi/lo
// CTA tile 128 rows x 128 cols (cols 0-63 -> K, 64-127 -> Q). BK=32.
// ===========================================================================
#define PJ_STRIDE 80
#define PJ_AH 0
#define PJ_AL 10240
#define PJ_BH 20480
#define PJ_BL 30720
#define PJ_SMEM 40960

__global__ __launch_bounds__(256, 1) void qkproj_mma(
    const float* __restrict__ A, const float* __restrict__ Wk,
    const float* __restrict__ Wq,
    __nv_bfloat16* __restrict__ Kh, __nv_bfloat16* __restrict__ Kl,
    __nv_bfloat16* __restrict__ Qh, __nv_bfloat16* __restrict__ Ql)
{
    extern __shared__ char sm[];
    const uint32_t smb = smem_u32(sm);
    const int tid = threadIdx.x, wid = tid >> 5, lane = tid & 31;
    const int g = lane >> 2, t = lane & 3;
    const int row0 = blockIdx.y * 128;
    const int m0 = (wid & 3) * 32, n0 = (wid >> 2) * 64;

    float o[16][4];
    #pragma unroll
    for (int i = 0; i < 16; i++)
        #pragma unroll
        for (int j = 0; j < 4; j++) o[i][j] = 0.f;

    const int lr = tid >> 1, lc0 = (tid & 1) * 16;
    const float* arow = A + (size_t)(row0 + lr) * EMB + lc0;
    const float* brow = (lr < 64 ? Wk + (size_t)lr * EMB
                                 : Wq + (size_t)(lr - 64) * EMB) + lc0;

    for (int kc = 0; kc < EMB / 32; kc++) {
        #pragma unroll
        for (int j = 0; j < 4; j++) {
            float4 va = *(const float4*)(arow + kc * 32 + j * 4);
            split_store4(va, sm + PJ_AH + lr * PJ_STRIDE + lc0 * 2 + j * 8,
                             sm + PJ_AL + lr * PJ_STRIDE + lc0 * 2 + j * 8);
            float4 vb = *(const float4*)(brow + kc * 32 + j * 4);
            split_store4(vb, sm + PJ_BH + lr * PJ_STRIDE + lc0 * 2 + j * 8,
                             sm + PJ_BL + lr * PJ_STRIDE + lc0 * 2 + j * 8);
        }
        __syncthreads();
        #pragma unroll
        for (int ks = 0; ks < 2; ks++) {
            uint32_t ah[2][4], al[2][4];
            #pragma unroll
            for (int mt = 0; mt < 2; mt++) {
                LDMX4(ah[mt], a_addr(smb + PJ_AH, m0 + mt*16, ks*32, lane, PJ_STRIDE));
                LDMX4(al[mt], a_addr(smb + PJ_AL, m0 + mt*16, ks*32, lane, PJ_STRIDE));
            }
            #pragma unroll
            for (int nt = 0; nt < 8; nt++) {
                uint32_t bh[2], bl[2];
                LDMX2(bh, b_addr(smb + PJ_BH, n0 + nt*8, ks*32, lane, PJ_STRIDE));
                LDMX2(bl, b_addr(smb + PJ_BL, n0 + nt*8, ks*32, lane, PJ_STRIDE));
                #pragma unroll
                for (int mt = 0; mt < 2; mt++)
                    MMA3(o[mt*8 + nt], ah[mt], al[mt], bh, bl);
            }
        }
        __syncthreads();
    }

    __nv_bfloat16* Ch = (n0 == 0) ? Kh : Qh;
    __nv_bfloat16* Cl = (n0 == 0) ? Kl : Ql;
    #pragma unroll
    for (int mt = 0; mt < 2; mt++)
        #pragma unroll
        for (int nt = 0; nt < 8; nt++) {
            const int r0 = row0 + m0 + mt*16 + g;
            const int c  = nt*8 + 2*t;
            uint32_t lo0, lo1;
            uint32_t hi0 = packsplit2(o[mt*8+nt][0], o[mt*8+nt][1], lo0);
            uint32_t hi1 = packsplit2(o[mt*8+nt][2], o[mt*8+nt][3], lo1);
            *(uint32_t*)(Ch + (size_t)r0 * HEADSZ + c)       = hi0;
            *(uint32_t*)(Cl + (size_t)r0 * HEADSZ + c)       = lo0;
            *(uint32_t*)(Ch + (size_t)(r0 + 8) * HEADSZ + c) = hi1;
            *(uint32_t*)(Cl + (size_t)(r0 + 8) * HEADSZ + c) = lo1;
        }
}

// ===========================================================================
// V projection (bf16x3 mma), outputs split bf16 hi/lo. Tile 128x128, BK=32.
// ===========================================================================
__global__ __launch_bounds__(256, 1) void vproj_mma(
    const float* __restrict__ A, const float* __restrict__ W,
    __nv_bfloat16* __restrict__ Vh, __nv_bfloat16* __restrict__ Vl)
{
    extern __shared__ char sm[];
    const uint32_t smb = smem_u32(sm);
    const int tid = threadIdx.x, wid = tid >> 5, lane = tid & 31;
    const int g = lane >> 2, t = lane & 3;
    const int row0 = blockIdx.y * 128;
    const int col0 = blockIdx.x * 128;
    const int m0 = (wid & 3) * 32, n0 = (wid >> 2) * 64;

    float o[16][4];
    #pragma unroll
    for (int i = 0; i < 16; i++)
        #pragma unroll
        for (int j = 0; j < 4; j++) o[i][j] = 0.f;

    const int lr = tid >> 1, lc0 = (tid & 1) * 16;
    const float* arow = A + (size_t)(row0 + lr) * EMB + lc0;
    const float* brow = W + (size_t)(col0 + lr) * EMB + lc0;

    for (int kc = 0; kc < EMB / 32; kc++) {
        #pragma unroll
        for (int j = 0; j < 4; j++) {
            float4 va = *(const float4*)(arow + kc * 32 + j * 4);
            split_store4(va, sm + PJ_AH + lr * PJ_STRIDE + lc0 * 2 + j * 8,
                             sm + PJ_AL + lr * PJ_STRIDE + lc0 * 2 + j * 8);
            float4 vb = *(const float4*)(brow + kc * 32 + j * 4);
            split_store4(vb, sm + PJ_BH + lr * PJ_STRIDE + lc0 * 2 + j * 8,
                             sm + PJ_BL + lr * PJ_STRIDE + lc0 * 2 + j * 8);
        }
        __syncthreads();
        #pragma unroll
        for (int ks = 0; ks < 2; ks++) {
            uint32_t ah[2][4], al[2][4];
            #pragma unroll
            for (int mt = 0; mt < 2; mt++) {
                LDMX4(ah[mt], a_addr(smb + PJ_AH, m0 + mt*16, ks*32, lane, PJ_STRIDE));
                LDMX4(al[mt], a_addr(smb + PJ_AL, m0 + mt*16, ks*32, lane, PJ_STRIDE));
            }
            #pragma unroll
            for (int nt = 0; nt < 8; nt++) {
                uint32_t bh[2], bl[2];
                LDMX2(bh, b_addr(smb + PJ_BH, n0 + nt*8, ks*32, lane, PJ_STRIDE));
                LDMX2(bl, b_addr(smb + PJ_BL, n0 + nt*8, ks*32, lane, PJ_STRIDE));
                #pragma unroll
                for (int mt = 0; mt < 2; mt++)
                    MMA3(o[mt*8 + nt], ah[mt], al[mt], bh, bl);
            }
        }
        __syncthreads();
    }

    #pragma unroll
    for (int mt = 0; mt < 2; mt++)
        #pragma unroll
        for (int nt = 0; nt < 8; nt++) {
            const int r0 = row0 + m0 + mt*16 + g;
            const int c  = col0 + n0 + nt*8 + 2*t;
            uint32_t lo0, lo1;
            uint32_t hi0 = packsplit2(o[mt*8+nt][0], o[mt*8+nt][1], lo0);
            uint32_t hi1 = packsplit2(o[mt*8+nt][2], o[mt*8+nt][3], lo1);
            *(uint32_t*)(Vh + (size_t)r0 * EMB + c)       = hi0;
            *(uint32_t*)(Vl + (size_t)r0 * EMB + c)       = lo0;
            *(uint32_t*)(Vh + (size_t)(r0 + 8) * EMB + c) = hi1;
            *(uint32_t*)(Vl + (size_t)(r0 + 8) * EMB + c) = lo1;
        }
}

// ===========================================================================
// Fused flash attention (bf16x3 mma, online softmax, cp.async double buffer).
// CTA: 128 queries x 128 output dims. 256 threads.
// S warps: warp w owns rows w*16..w*16+15 (full 64-key width -> in-warp stats)
// PV warps: rows (w&3)*32, cols (w>>2)*64.
// ===========================================================================
#define ATT_SCALE 0                       // 128 f32 per-tile rescale
#define ATT_LINV  512                     // 128 f32 final 1/l
#define ATT_QH    1024
#define ATT_QL    (ATT_QH + 128*144)      // 19456
#define ATT_KSTG  (64*144)                // 9216 per stage
#define ATT_KH    (ATT_QL + 128*144)      // 37888  (+stg*ATT_KSTG)
#define ATT_KL    (ATT_KH + 2*ATT_KSTG)   // 56320
#define ATT_VSTG  (64*272)                // 17408 per stage
#define ATT_VH    (ATT_KL + 2*ATT_KSTG)   // 74752  (+stg*ATT_VSTG)
#define ATT_VL    (ATT_VH + 2*ATT_VSTG)   // 109568
#define ATT_PH    (ATT_VL + 2*ATT_VSTG)   // 144384
#define ATT_PL    (ATT_PH + 128*144)      // 162816
#define ATT_SMEM  (ATT_PL + 128*144)      // 181248

__global__ __launch_bounds__(256, 1) void attn_fused(
    const __nv_bfloat16* __restrict__ Qh, const __nv_bfloat16* __restrict__ Ql,
    const __nv_bfloat16* __restrict__ Kh, const __nv_bfloat16* __restrict__ Kl,
    const __nv_bfloat16* __restrict__ Vh, const __nv_bfloat16* __restrict__ Vl,
    float* __restrict__ out)
{
    extern __shared__ char sm[];
    const uint32_t smb = smem_u32(sm);
    float* smf = (float*)sm;
    const int tid = threadIdx.x, wid = tid >> 5, lane = tid & 31;
    const int g = lane >> 2, t = lane & 3;
    const int blk = blockIdx.z;
    const int qt = (SEQ/128 - 1) - blockIdx.y;
    const int q0 = qt * 128;
    const int d0 = blockIdx.x * 128;
    const int nkt = 2*qt + 2;

    const size_t tok0 = (size_t)blk * SEQ;

    // ---- issue Q load (cp.async), rows 128 x 128B per array ----
    {
        const int r = tid >> 1, h = tid & 1;
        const char* gqh = (const char*)(Qh + (tok0 + q0 + r) * HEADSZ) + h*64;
        const char* gql = (const char*)(Ql + (tok0 + q0 + r) * HEADSZ) + h*64;
        uint32_t dq = smb + ATT_QH + r*144 + h*64;
        #pragma unroll
        for (int j = 0; j < 4; j++) {
            CPA16(dq + j*16, gqh + j*16);
            CPA16(dq + (ATT_QL - ATT_QH) + j*16, gql + j*16);
        }
    }
    // ---- K/V tile loader ----
    auto load_kv = [&](int kt, int stg) {
        const size_t key = tok0 + kt*64 + (tid >> 2);
        // K: 64 rows x 128B, thread: row tid>>2, chunks (tid&3)*2 + j
        {
            const char* gk  = (const char*)(Kh + key * HEADSZ);
            const char* gkl = (const char*)(Kl + key * HEADSZ);
            uint32_t dk = smb + ATT_KH + stg*ATT_KSTG + (tid>>2)*144 + (tid&3)*32;
            #pragma unroll
            for (int j = 0; j < 2; j++) {
                CPA16(dk + j*16, gk + (tid&3)*32 + j*16);
                CPA16(dk + (ATT_KL - ATT_KH) + j*16, gkl + (tid&3)*32 + j*16);
            }
        }
        // V: 64 rows x 256B (128-dim slice), thread: row tid>>2, 4 chunks
        {
            const char* gv  = (const char*)(Vh + key * EMB + d0) + (tid&3)*64;
            const char* gvl = (const char*)(Vl + key * EMB + d0) + (tid&3)*64;
            uint32_t dv = smb + ATT_VH + stg*ATT_VSTG + (tid>>2)*272 + (tid&3)*64;
            #pragma unroll
            for (int j = 0; j < 4; j++) {
                CPA16(dv + j*16, gv + j*16);
                CPA16(dv + (ATT_VL - ATT_VH) + j*16, gvl + j*16);
            }
        }
    };

    load_kv(0, 0);
    CPA_COMMIT();                 // group: Q + KV0
    CPA_WAIT(0);
    __syncthreads();

    // ---- Q fragments register-resident ----
    const int m0s = wid * 16;
    uint32_t qah[4][4], qal[4][4];
    #pragma unroll
    for (int ks = 0; ks < 4; ks++) {
        LDMX4(qah[ks], a_addr(smb + ATT_QH, m0s, ks*32, lane, 144));
        LDMX4(qal[ks], a_addr(smb + ATT_QL, m0s, ks*32, lane, 144));
    }

    const int m0p = (wid & 3) * 32, n0p = (wid >> 2) * 64;
    float m0 = -1e30f, m1 = -1e30f, l0 = 0.f, l1 = 0.f;
    float o[16][4];
    #pragma unroll
    for (int i = 0; i < 16; i++)
        #pragma unroll
        for (int j = 0; j < 4; j++) o[i][j] = 0.f;

    const int qr0 = q0 + m0s + g, qr1 = qr0 + 8;

    for (int kt = 0; kt < nkt; kt++) {
        const int stg = kt & 1;
        if (kt + 1 < nkt) {
            load_kv(kt + 1, (kt + 1) & 1);
            CPA_COMMIT();
            CPA_WAIT(1);
        } else {
            CPA_WAIT(0);
        }
        __syncthreads();          // stage stg ready everywhere

        // ---- S = Q @ K^T (16 rows x 64 cols per warp) ----
        float s[8][4];
        #pragma unroll
        for (int i = 0; i < 8; i++)
            #pragma unroll
            for (int j = 0; j < 4; j++) s[i][j] = 0.f;
        const uint32_t kbh = smb + ATT_KH + stg*ATT_KSTG;
        const uint32_t kbl = smb + ATT_KL + stg*ATT_KSTG;
        #pragma unroll
        for (int ks = 0; ks < 4; ks++) {
            #pragma unroll
            for (int nt = 0; nt < 8; nt++) {
                uint32_t bh[2], bl[2];
                LDMX2(bh, b_addr(kbh, nt*8, ks*32, lane, 144));
                LDMX2(bl, b_addr(kbl, nt*8, ks*32, lane, 144));
                MMA3(s[nt], qah[ks], qal[ks], bh, bl);
            }
        }

        // ---- online softmax (in-warp: each warp owns its rows) ----
        float mx0 = -1e30f, mx1 = -1e30f;
        #pragma unroll
        for (int nt = 0; nt < 8; nt++) {
            const int kc = kt*64 + nt*8 + 2*t;
            s[nt][0] = (kc     <= qr0) ? s[nt][0]*0.125f : -1e30f;
            s[nt][1] = (kc + 1 <= qr0) ? s[nt][1]*0.125f : -1e30f;
            s[nt][2] = (kc     <= qr1) ? s[nt][2]*0.125f : -1e30f;
            s[nt][3] = (kc + 1 <= qr1) ? s[nt][3]*0.125f : -1e30f;
            mx0 = fmaxf(mx0, fmaxf(s[nt][0], s[nt][1]));
            mx1 = fmaxf(mx1, fmaxf(s[nt][2], s[nt][3]));
        }
        mx0 = fmaxf(mx0, __shfl_xor_sync(0xffffffffu, mx0, 1));
        mx0 = fmaxf(mx0, __shfl_xor_sync(0xffffffffu, mx0, 2));
        mx1 = fmaxf(mx1, __shfl_xor_sync(0xffffffffu, mx1, 1));
        mx1 = fmaxf(mx1, __shfl_xor_sync(0xffffffffu, mx1, 2));
        const float m0n = fmaxf(m0, mx0), m1n = fmaxf(m1, mx1);
        const float sc0 = __expf(m0 - m0n), sc1 = __expf(m1 - m1n);
        float sum0 = 0.f, sum1 = 0.f;
        #pragma unroll
        for (int nt = 0; nt < 8; nt++) {
            float p0 = __expf(s[nt][0] - m0n);
            float p1 = __expf(s[nt][1] - m0n);
            float p2 = __expf(s[nt][2] - m1n);
            float p3 = __expf(s[nt][3] - m1n);
            sum0 += p0 + p1; sum1 += p2 + p3;
            const int cb = (nt*8 + 2*t) * 2;
            uint32_t lo0, lo1;
            uint32_t hi0 = packsplit2(p0, p1, lo0);
            uint32_t hi1 = packsplit2(p2, p3, lo1);
            *(uint32_t*)(sm + ATT_PH + (m0s+g)*144   + cb) = hi0;
            *(uint32_t*)(sm + ATT_PL + (m0s+g)*144   + cb) = lo0;
            *(uint32_t*)(sm + ATT_PH + (m0s+8+g)*144 + cb) = hi1;
            *(uint32_t*)(sm + ATT_PL + (m0s+8+g)*144 + cb) = lo1;
        }
        sum0 += __shfl_xor_sync(0xffffffffu, sum0, 1);
        sum0 += __shfl_xor_sync(0xffffffffu, sum0, 2);
        sum1 += __shfl_xor_sync(0xffffffffu, sum1, 1);
        sum1 += __shfl_xor_sync(0xffffffffu, sum1, 2);
        l0 = l0*sc0 + sum0; l1 = l1*sc1 + sum1;
        m0 = m0n; m1 = m1n;
        if (t == 0) {
            smf[ATT_SCALE/4 + m0s + g]     = sc0;
            smf[ATT_SCALE/4 + m0s + 8 + g] = sc1;
        }
        __syncthreads();          // P + scale visible

        // ---- PV: rescale accumulators, O += P @ V ----
        {
            const float f00 = smf[ATT_SCALE/4 + m0p + g];
            const float f01 = smf[ATT_SCALE/4 + m0p + 8 + g];
            const float f10 = smf[ATT_SCALE/4 + m0p + 16 + g];
            const float f11 = smf[ATT_SCALE/4 + m0p + 24 + g];
            #pragma unroll
            for (int nt = 0; nt < 8; nt++) {
                o[nt][0] *= f00; o[nt][1] *= f00;
                o[nt][2] *= f01; o[nt][3] *= f01;
                o[8+nt][0] *= f10; o[8+nt][1] *= f10;
                o[8+nt][2] *= f11; o[8+nt][3] *= f11;
            }
        }
        const uint32_t vbh = smb + ATT_VH + stg*ATT_VSTG + (uint32_t)(lane & 15)*272
                           + (uint32_t)n0p*2;
        const uint32_t vbl = vbh + (ATT_VL - ATT_VH);
        #pragma unroll
        for (int ks = 0; ks < 4; ks++) {
            uint32_t pah[2][4], pal[2][4];
            #pragma unroll
            for (int mt = 0; mt < 2; mt++) {
                LDMX4(pah[mt], a_addr(smb + ATT_PH, m0p + mt*16, ks*32, lane, 144));
                LDMX4(pal[mt], a_addr(smb + ATT_PL, m0p + mt*16, ks*32, lane, 144));
            }
            #pragma unroll
            for (int nt = 0; nt < 8; nt++) {
                uint32_t bh[2], bl[2];
                LDMX2T(bh, vbh + ks*16*272 + nt*16);
                LDMX2T(bl, vbl + ks*16*272 + nt*16);
                #pragma unroll
                for (int mt = 0; mt < 2; mt++)
                    MMA3(o[mt*8 + nt], pah[mt], pal[mt], bh, bl);
            }
        }
        __syncthreads();          // protect P + stage buffers for next iter
    }

    // ---- final 1/l broadcast, normalize, store ----
    if (t == 0) {
        smf[ATT_LINV/4 + m0s + g]     = 1.f / l0;
        smf[ATT_LINV/4 + m0s + 8 + g] = 1.f / l1;
    }
    __syncthreads();
    #pragma unroll
    for (int mt = 0; mt < 2; mt++) {
        const int r0 = m0p + mt*16 + g;
        const float i0 = smf[ATT_LINV/4 + r0];
        const float i1 = smf[ATT_LINV/4 + r0 + 8];
        #pragma unroll
        for (int nt = 0; nt < 8; nt++) {
            const int c = d0 + n0p + nt*8 + 2*t;
            float2 v0 = make_float2(o[mt*8+nt][0]*i0, o[mt*8+nt][1]*i0);
            float2 v1 = make_float2(o[mt*8+nt][2]*i1, o[mt*8+nt][3]*i1);
            *(float2*)(out + (tok0 + q0 + r0)     * EMB + c) = v0;
            *(float2*)(out + (tok0 + q0 + r0 + 8) * EMB + c) = v1;
        }
    }
}

// ===========================================================================
extern "C" void kernel_launch(void* const* d_in, const int* in_sizes, int n_in,
                              void* d_out, int out_size)
{
    const float* x  = (const float*)d_in[0];
    const float* Wk = (const float*)d_in[1];
    const float* Wq = (const float*)d_in[2];
    const float* Wv = (const float*)d_in[3];
    float* out = (float*)d_out;

    __nv_bfloat16 *Qh, *Ql, *Kh, *Kl, *Vh, *Vl;
    cudaGetSymbolAddress((void**)&Qh, g_Qh);
    cudaGetSymbolAddress((void**)&Ql, g_Ql);
    cudaGetSymbolAddress((void**)&Kh, g_Kh);
    cudaGetSymbolAddress((void**)&Kl, g_Kl);
    cudaGetSymbolAddress((void**)&Vh, g_Vh);
    cudaGetSymbolAddress((void**)&Vl, g_Vl);

    cudaFuncSetAttribute(qkproj_mma, cudaFuncAttributeMaxDynamicSharedMemorySize, PJ_SMEM);
    cudaFuncSetAttribute(vproj_mma,  cudaFuncAttributeMaxDynamicSharedMemorySize, PJ_SMEM);
    cudaFuncSetAttribute(attn_fused, cudaFuncAttributeMaxDynamicSharedMemorySize, ATT_SMEM);

    qkproj_mma<<<dim3(1, BT/128), 256, PJ_SMEM>>>(x, Wk, Wq, Kh, Kl, Qh, Ql);
    vproj_mma<<<dim3(EMB/128, BT/128), 256, PJ_SMEM>>>(x, Wv, Vh, Vl);
    attn_fused<<<dim3(EMB/128, SEQ/128, BATCH), 256, ATT_SMEM>>>(
        Qh, Ql, Kh, Kl, Vh, Vl, out);
}

// round 7
// speedup vs baseline: 2.9612x; 1.2025x over previous
#include <cuda_runtime.h>
#include <cuda_bf16.h>
#include <cstdint>

#define HEADSZ 64
#define EMB    1024
#define BATCH  4
#define SEQ    4096
#define BT     (BATCH*SEQ)

// Scratch (allocation-free)
__device__ __nv_bfloat16 g_Qh[(size_t)BT*HEADSZ];
__device__ __nv_bfloat16 g_Ql[(size_t)BT*HEADSZ];
__device__ __nv_bfloat16 g_Kh[(size_t)BT*HEADSZ];
__device__ __nv_bfloat16 g_Kl[(size_t)BT*HEADSZ];
__device__ __nv_bfloat16 g_Vh[(size_t)BT*EMB];
__device__ __nv_bfloat16 g_Vl[(size_t)BT*EMB];

// ===========================================================================
// helpers
// ===========================================================================
__device__ __forceinline__ uint32_t smem_u32(const void* p) {
    uint32_t a;
    asm("{ .reg .u64 t; cvta.to.shared.u64 t, %1; cvt.u32.u64 %0, t; }"
        : "=r"(a) : "l"(p));
    return a;
}

#define LDMX4(r, a) \
    asm volatile("ldmatrix.sync.aligned.m8n8.x4.shared.b16 {%0,%1,%2,%3}, [%4];" \
        : "=r"((r)[0]), "=r"((r)[1]), "=r"((r)[2]), "=r"((r)[3]) : "r"(a))
#define LDMX2(r, a) \
    asm volatile("ldmatrix.sync.aligned.m8n8.x2.shared.b16 {%0,%1}, [%2];" \
        : "=r"((r)[0]), "=r"((r)[1]) : "r"(a))
#define LDMX4T(r, a) \
    asm volatile("ldmatrix.sync.aligned.m8n8.x4.trans.shared.b16 {%0,%1,%2,%3}, [%4];" \
        : "=r"((r)[0]), "=r"((r)[1]), "=r"((r)[2]), "=r"((r)[3]) : "r"(a))

#define MMA_BF16(d, a, b) \
    asm volatile("mma.sync.aligned.m16n8k16.row.col.f32.bf16.bf16.f32 " \
        "{%0,%1,%2,%3}, {%4,%5,%6,%7}, {%8,%9}, {%0,%1,%2,%3};" \
        : "+f"((d)[0]), "+f"((d)[1]), "+f"((d)[2]), "+f"((d)[3]) \
        : "r"((a)[0]), "r"((a)[1]), "r"((a)[2]), "r"((a)[3]), \
          "r"((b)[0]), "r"((b)[1]))

#define MMA3(d, ah, al, bh, bl) do { \
    MMA_BF16(d, ah, bh); MMA_BF16(d, ah, bl); MMA_BF16(d, al, bh); } while (0)

#define MMA_TF32(d, a, b0, b1) \
    asm volatile("mma.sync.aligned.m16n8k8.row.col.f32.tf32.tf32.f32 " \
        "{%0,%1,%2,%3}, {%4,%5,%6,%7}, {%8,%9}, {%0,%1,%2,%3};" \
        : "+f"((d)[0]), "+f"((d)[1]), "+f"((d)[2]), "+f"((d)[3]) \
        : "r"((a)[0]), "r"((a)[1]), "r"((a)[2]), "r"((a)[3]), \
          "r"(b0), "r"(b1))

#define CPA16(dst, src) \
    asm volatile("cp.async.cg.shared.global [%0], [%1], 16;" :: "r"(dst), "l"(src))
#define CPA_COMMIT() asm volatile("cp.async.commit_group;" ::: "memory")
#define CPA_WAIT(n)  asm volatile("cp.async.wait_group %0;" :: "n"(n) : "memory")

__device__ __forceinline__ uint32_t a_addr(uint32_t base, int row, int kbyte,
                                           int lane, int strideB) {
    return base + (uint32_t)(row + (lane & 15)) * strideB + kbyte +
           ((lane >> 4) << 4);
}

__device__ __forceinline__ uint32_t bpack(__nv_bfloat16 a, __nv_bfloat16 b) {
    return ((uint32_t)__bfloat16_as_ushort(b) << 16) |
           (uint32_t)__bfloat16_as_ushort(a);
}
__device__ __forceinline__ uint32_t packsplit2(float a, float b, uint32_t& lo) {
    __nv_bfloat16 ha = __float2bfloat16_rn(a), hb = __float2bfloat16_rn(b);
    lo = bpack(__float2bfloat16_rn(a - __bfloat162float(ha)),
               __float2bfloat16_rn(b - __bfloat162float(hb)));
    return bpack(ha, hb);
}
__device__ __forceinline__ void split_store4(float4 v, char* ph, char* pl) {
    uint32_t l0, l1;
    uint32_t h0 = packsplit2(v.x, v.y, l0);
    uint32_t h1 = packsplit2(v.z, v.w, l1);
    uint2 h; h.x = h0; h.y = h1;
    uint2 l; l.x = l0; l.y = l1;
    *(uint2*)ph = h;
    *(uint2*)pl = l;
}
__device__ __forceinline__ uint32_t f2tf32(float x) {
    uint32_t u;
    asm("cvt.rna.tf32.f32 %0, %1;" : "=r"(u) : "f"(x));
    return u;
}

// ===========================================================================
// Fused Q/K projection (bf16x3) -> split bf16 hi/lo. (unchanged, works)
// ===========================================================================
#define PJ_STRIDE 80
#define PJ_AH 0
#define PJ_AL 10240
#define PJ_BH 20480
#define PJ_BL 30720
#define PJ_SMEM 40960

__device__ __forceinline__ uint32_t b_addr2(uint32_t base, int row, int kbyte,
                                            int lane, int strideB) {
    return base + (uint32_t)(row + (lane & 7)) * strideB + kbyte +
           (((lane >> 3) & 1) << 4);
}

__global__ __launch_bounds__(256, 1) void qkproj_mma(
    const float* __restrict__ A, const float* __restrict__ Wk,
    const float* __restrict__ Wq,
    __nv_bfloat16* __restrict__ Kh, __nv_bfloat16* __restrict__ Kl,
    __nv_bfloat16* __restrict__ Qh, __nv_bfloat16* __restrict__ Ql)
{
    extern __shared__ char sm[];
    const uint32_t smb = smem_u32(sm);
    const int tid = threadIdx.x, wid = tid >> 5, lane = tid & 31;
    const int g = lane >> 2, t = lane & 3;
    const int row0 = blockIdx.y * 128;
    const int m0 = (wid & 3) * 32, n0 = (wid >> 2) * 64;

    float o[16][4];
    #pragma unroll
    for (int i = 0; i < 16; i++)
        #pragma unroll
        for (int j = 0; j < 4; j++) o[i][j] = 0.f;

    const int lr = tid >> 1, lc0 = (tid & 1) * 16;
    const float* arow = A + (size_t)(row0 + lr) * EMB + lc0;
    const float* brow = (lr < 64 ? Wk + (size_t)lr * EMB
                                 : Wq + (size_t)(lr - 64) * EMB) + lc0;

    for (int kc = 0; kc < EMB / 32; kc++) {
        #pragma unroll
        for (int j = 0; j < 4; j++) {
            float4 va = *(const float4*)(arow + kc * 32 + j * 4);
            split_store4(va, sm + PJ_AH + lr * PJ_STRIDE + lc0 * 2 + j * 8,
                             sm + PJ_AL + lr * PJ_STRIDE + lc0 * 2 + j * 8);
            float4 vb = *(const float4*)(brow + kc * 32 + j * 4);
            split_store4(vb, sm + PJ_BH + lr * PJ_STRIDE + lc0 * 2 + j * 8,
                             sm + PJ_BL + lr * PJ_STRIDE + lc0 * 2 + j * 8);
        }
        __syncthreads();
        #pragma unroll
        for (int ks = 0; ks < 2; ks++) {
            uint32_t ah[2][4], al[2][4];
            #pragma unroll
            for (int mt = 0; mt < 2; mt++) {
                LDMX4(ah[mt], a_addr(smb + PJ_AH, m0 + mt*16, ks*32, lane, PJ_STRIDE));
                LDMX4(al[mt], a_addr(smb + PJ_AL, m0 + mt*16, ks*32, lane, PJ_STRIDE));
            }
            #pragma unroll
            for (int nt = 0; nt < 8; nt++) {
                uint32_t bh[2], bl[2];
                LDMX2(bh, b_addr2(smb + PJ_BH, n0 + nt*8, ks*32, lane, PJ_STRIDE));
                LDMX2(bl, b_addr2(smb + PJ_BL, n0 + nt*8, ks*32, lane, PJ_STRIDE));
                #pragma unroll
                for (int mt = 0; mt < 2; mt++)
                    MMA3(o[mt*8 + nt], ah[mt], al[mt], bh, bl);
            }
        }
        __syncthreads();
    }

    __nv_bfloat16* Ch = (n0 == 0) ? Kh : Qh;
    __nv_bfloat16* Cl = (n0 == 0) ? Kl : Ql;
    #pragma unroll
    for (int mt = 0; mt < 2; mt++)
        #pragma unroll
        for (int nt = 0; nt < 8; nt++) {
            const int r0 = row0 + m0 + mt*16 + g;
            const int c  = nt*8 + 2*t;
            uint32_t lo0, lo1;
            uint32_t hi0 = packsplit2(o[mt*8+nt][0], o[mt*8+nt][1], lo0);
            uint32_t hi1 = packsplit2(o[mt*8+nt][2], o[mt*8+nt][3], lo1);
            *(uint32_t*)(Ch + (size_t)r0 * HEADSZ + c)       = hi0;
            *(uint32_t*)(Cl + (size_t)r0 * HEADSZ + c)       = lo0;
            *(uint32_t*)(Ch + (size_t)(r0 + 8) * HEADSZ + c) = hi1;
            *(uint32_t*)(Cl + (size_t)(r0 + 8) * HEADSZ + c) = lo1;
        }
}

// ===========================================================================
// V projection: single-pass tf32 m16n8k8.  C = x @ Wv^T, split to bf16 hi/lo.
// Tile 128x128, BK=32, 256 threads.
// ===========================================================================
#define VP_SMEM (2 * 128 * 36 * 4)      // 36864

__global__ __launch_bounds__(256, 1) void vproj_tf32(
    const float* __restrict__ A, const float* __restrict__ W,
    __nv_bfloat16* __restrict__ Vh, __nv_bfloat16* __restrict__ Vl)
{
    extern __shared__ char sm[];
    uint32_t* As = (uint32_t*)sm;            // [128][36]
    uint32_t* Bs = As + 128*36;              // [128][36]
    const int tid = threadIdx.x, wid = tid >> 5, lane = tid & 31;
    const int g = lane >> 2, t = lane & 3;
    const int row0 = blockIdx.y * 128;
    const int col0 = blockIdx.x * 128;
    const int m0 = (wid & 3) * 32, n0 = (wid >> 2) * 64;

    float o[16][4];
    #pragma unroll
    for (int i = 0; i < 16; i++)
        #pragma unroll
        for (int j = 0; j < 4; j++) o[i][j] = 0.f;

    const int lr = tid >> 1, lc0 = (tid & 1) * 16;
    const float* arow = A + (size_t)(row0 + lr) * EMB + lc0;
    const float* brow = W + (size_t)(col0 + lr) * EMB + lc0;

    for (int kc = 0; kc < EMB / 32; kc++) {
        #pragma unroll
        for (int j = 0; j < 4; j++) {
            float4 va = *(const float4*)(arow + kc * 32 + j * 4);
            As[lr*36 + lc0 + j*4 + 0] = f2tf32(va.x);
            As[lr*36 + lc0 + j*4 + 1] = f2tf32(va.y);
            As[lr*36 + lc0 + j*4 + 2] = f2tf32(va.z);
            As[lr*36 + lc0 + j*4 + 3] = f2tf32(va.w);
            float4 vb = *(const float4*)(brow + kc * 32 + j * 4);
            Bs[lr*36 + lc0 + j*4 + 0] = f2tf32(vb.x);
            Bs[lr*36 + lc0 + j*4 + 1] = f2tf32(vb.y);
            Bs[lr*36 + lc0 + j*4 + 2] = f2tf32(vb.z);
            Bs[lr*36 + lc0 + j*4 + 3] = f2tf32(vb.w);
        }
        __syncthreads();
        #pragma unroll
        for (int ks = 0; ks < 4; ks++) {
            uint32_t a[2][4];
            #pragma unroll
            for (int mt = 0; mt < 2; mt++) {
                const int r = m0 + mt*16;
                a[mt][0] = As[(r + g)*36     + ks*8 + t];
                a[mt][1] = As[(r + 8 + g)*36 + ks*8 + t];
                a[mt][2] = As[(r + g)*36     + ks*8 + t + 4];
                a[mt][3] = As[(r + 8 + g)*36 + ks*8 + t + 4];
            }
            #pragma unroll
            for (int nt = 0; nt < 8; nt++) {
                uint32_t b0 = Bs[(n0 + nt*8 + g)*36 + ks*8 + t];
                uint32_t b1 = Bs[(n0 + nt*8 + g)*36 + ks*8 + t + 4];
                #pragma unroll
                for (int mt = 0; mt < 2; mt++)
                    MMA_TF32(o[mt*8 + nt], a[mt], b0, b1);
            }
        }
        __syncthreads();
    }

    #pragma unroll
    for (int mt = 0; mt < 2; mt++)
        #pragma unroll
        for (int nt = 0; nt < 8; nt++) {
            const int r0 = row0 + m0 + mt*16 + g;
            const int c  = col0 + n0 + nt*8 + 2*t;
            uint32_t lo0, lo1;
            uint32_t hi0 = packsplit2(o[mt*8+nt][0], o[mt*8+nt][1], lo0);
            uint32_t hi1 = packsplit2(o[mt*8+nt][2], o[mt*8+nt][3], lo1);
            *(uint32_t*)(Vh + (size_t)r0 * EMB + c)       = hi0;
            *(uint32_t*)(Vl + (size_t)r0 * EMB + c)       = lo0;
            *(uint32_t*)(Vh + (size_t)(r0 + 8) * EMB + c) = hi1;
            *(uint32_t*)(Vl + (size_t)(r0 + 8) * EMB + c) = lo1;
        }
}

// ===========================================================================
// Fused flash attention, 512 threads, CTA = 128 queries x 256 dims.
// S warps (16): rows (w&7)*16, col-half (w>>3)*32; stats via smem exchange.
// PV warps (16): rows (w&3)*32, cols (w>>2)*64.
// K double-buffered (prefetch), V prefetched at iteration top.
// ===========================================================================
#define ATS_M    0                         // m ping-pong [2][128] f32
#define ATS_L    1024                      // l [128]
#define ATS_SC   1536                      // scale [128]
#define ATS_PMX  2048                      // pmax [2][128]
#define ATS_PSM  3072                      // psum [2][128]
#define AT2_QH   4096                      // 128 x 144B
#define AT2_QL   22528
#define AT2_K    40960                     // + stg*18432 ; hi +0, lo +9216
#define AT2_VH   77824                     // 64 x 528B
#define AT2_VL   111616
#define AT2_PH   145408                    // 128 x 144B
#define AT2_PL   163840
#define AT2_SMEM 182272

__global__ __launch_bounds__(512, 1) void attn_fused(
    const __nv_bfloat16* __restrict__ Qh, const __nv_bfloat16* __restrict__ Ql,
    const __nv_bfloat16* __restrict__ Kh, const __nv_bfloat16* __restrict__ Kl,
    const __nv_bfloat16* __restrict__ Vh, const __nv_bfloat16* __restrict__ Vl,
    float* __restrict__ out)
{
    extern __shared__ char sm[];
    const uint32_t smb = smem_u32(sm);
    float* smf = (float*)sm;
    const int tid = threadIdx.x, wid = tid >> 5, lane = tid & 31;
    const int g = lane >> 2, t = lane & 3;
    const int qt = (SEQ/128 - 1) - blockIdx.y;
    const int q0 = qt * 128;
    const int d0 = blockIdx.x * 256;
    const int nkt = 2*qt + 2;
    const size_t tok0 = (size_t)blockIdx.z * SEQ;

    // S mapping
    const int rs = (wid & 7) * 16;
    const int ch = wid >> 3;
    // PV mapping
    const int mp = (wid & 3) * 32;
    const int np = (wid >> 2) * 64;

    // ---- loaders ----
    auto load_k = [&](int kt, int stg) {
        const int row = tid >> 3, c = (tid & 7) * 16;
        const size_t key = tok0 + kt*64 + row;
        const uint32_t dk = smb + AT2_K + stg*18432 + row*144 + c;
        CPA16(dk,        (const char*)(Kh + key * HEADSZ) + c);
        CPA16(dk + 9216, (const char*)(Kl + key * HEADSZ) + c);
    };
    auto load_v = [&](int kt) {
        const int row = tid >> 3, c = (tid & 7) * 64;
        const size_t key = tok0 + kt*64 + row;
        const char* gvh = (const char*)(Vh + key * EMB + d0) + c;
        const char* gvl = (const char*)(Vl + key * EMB + d0) + c;
        const uint32_t dv = smb + AT2_VH + row*528 + c;
        #pragma unroll
        for (int j = 0; j < 4; j++) {
            CPA16(dv + j*16, gvh + j*16);
            CPA16(dv + (AT2_VL - AT2_VH) + j*16, gvl + j*16);
        }
    };

    // ---- prologue: Q + K0 + V0 (G0), K1 (G1) ----
    {
        const int row = tid >> 2, c = (tid & 3) * 32;
        const char* gqh = (const char*)(Qh + (tok0 + q0 + row) * HEADSZ) + c;
        const char* gql = (const char*)(Ql + (tok0 + q0 + row) * HEADSZ) + c;
        const uint32_t dq = smb + AT2_QH + row*144 + c;
        #pragma unroll
        for (int j = 0; j < 2; j++) {
            CPA16(dq + j*16, gqh + j*16);
            CPA16(dq + (AT2_QL - AT2_QH) + j*16, gql + j*16);
        }
    }
    load_k(0, 0);
    load_v(0);
    CPA_COMMIT();
    if (nkt > 1) load_k(1, 1);
    CPA_COMMIT();

    if (tid < 128) {
        smf[ATS_M/4 + tid] = -1e30f;
        smf[ATS_L/4 + tid] = 0.f;
    }

    float o[16][4];
    #pragma unroll
    for (int i = 0; i < 16; i++)
        #pragma unroll
        for (int j = 0; j < 4; j++) o[i][j] = 0.f;

    const int qr0 = q0 + rs + g, qr1 = qr0 + 8;
    const int r0 = rs + g, r1 = rs + 8 + g;

    for (int kt = 0; kt < nkt; kt++) {
        const int stg = kt & 1;
        const int par = kt & 1;
        if (kt > 0) {
            __syncthreads();                   // V + K-stage reuse safe
            load_v(kt);
            CPA_COMMIT();
            if (kt + 1 < nkt) load_k(kt + 1, stg ^ 1);
            CPA_COMMIT();
            CPA_WAIT(2);                       // K(kt) ready
        } else {
            CPA_WAIT(1);                       // Q,K0,V0 ready
        }
        __syncthreads();

        // ---- S = Q @ K^T : 16 rows x 32 cols per warp ----
        const uint32_t kh = smb + AT2_K + stg*18432;
        float s[4][4];
        #pragma unroll
        for (int i = 0; i < 4; i++)
            #pragma unroll
            for (int j = 0; j < 4; j++) s[i][j] = 0.f;

        #pragma unroll
        for (int ks = 0; ks < 4; ks++) {
            uint32_t qh4[4], ql4[4];
            LDMX4(qh4, a_addr(smb + AT2_QH, rs, ks*32, lane, 144));
            LDMX4(ql4, a_addr(smb + AT2_QL, rs, ks*32, lane, 144));
            #pragma unroll
            for (int ntp = 0; ntp < 2; ntp++) {
                uint32_t bh4[4], bl4[4];
                const uint32_t ka = kh +
                    (uint32_t)(ch*32 + ntp*16 + (lane & 7) + ((lane >> 4) << 3)) * 144
                    + ks*32 + (((lane >> 3) & 1) << 4);
                LDMX4(bh4, ka);
                LDMX4(bl4, ka + 9216);
                MMA3(s[2*ntp],     qh4, ql4, bh4,     bl4);
                MMA3(s[2*ntp + 1], qh4, ql4, bh4 + 2, bl4 + 2);
            }
        }

        // ---- mask + partial max ----
        float mx0 = -1e30f, mx1 = -1e30f;
        #pragma unroll
        for (int nt = 0; nt < 4; nt++) {
            const int c = kt*64 + ch*32 + nt*8 + 2*t;
            s[nt][0] = (c     <= qr0) ? s[nt][0]*0.125f : -1e30f;
            s[nt][1] = (c + 1 <= qr0) ? s[nt][1]*0.125f : -1e30f;
            s[nt][2] = (c     <= qr1) ? s[nt][2]*0.125f : -1e30f;
            s[nt][3] = (c + 1 <= qr1) ? s[nt][3]*0.125f : -1e30f;
            mx0 = fmaxf(mx0, fmaxf(s[nt][0], s[nt][1]));
            mx1 = fmaxf(mx1, fmaxf(s[nt][2], s[nt][3]));
        }
        mx0 = fmaxf(mx0, __shfl_xor_sync(0xffffffffu, mx0, 1));
        mx0 = fmaxf(mx0, __shfl_xor_sync(0xffffffffu, mx0, 2));
        mx1 = fmaxf(mx1, __shfl_xor_sync(0xffffffffu, mx1, 1));
        mx1 = fmaxf(mx1, __shfl_xor_sync(0xffffffffu, mx1, 2));
        if (t == 0) {
            smf[ATS_PMX/4 + ch*128 + r0] = mx0;
            smf[ATS_PMX/4 + ch*128 + r1] = mx1;
        }
        __syncthreads();

        // ---- combine max, exp, store P, partial sums ----
        const float mo0 = smf[ATS_M/4 + par*128 + r0];
        const float mo1 = smf[ATS_M/4 + par*128 + r1];
        const float mn0 = fmaxf(mo0, fmaxf(smf[ATS_PMX/4 + r0], smf[ATS_PMX/4 + 128 + r0]));
        const float mn1 = fmaxf(mo1, fmaxf(smf[ATS_PMX/4 + r1], smf[ATS_PMX/4 + 128 + r1]));
        float sum0 = 0.f, sum1 = 0.f;
        #pragma unroll
        for (int nt = 0; nt < 4; nt++) {
            float p0 = __expf(s[nt][0] - mn0);
            float p1 = __expf(s[nt][1] - mn0);
            float p2 = __expf(s[nt][2] - mn1);
            float p3 = __expf(s[nt][3] - mn1);
            sum0 += p0 + p1; sum1 += p2 + p3;
            const int cb = (ch*32 + nt*8 + 2*t) * 2;
            uint32_t lo0, lo1;
            uint32_t hi0 = packsplit2(p0, p1, lo0);
            uint32_t hi1 = packsplit2(p2, p3, lo1);
            *(uint32_t*)(sm + AT2_PH + r0*144 + cb) = hi0;
            *(uint32_t*)(sm + AT2_PL + r0*144 + cb) = lo0;
            *(uint32_t*)(sm + AT2_PH + r1*144 + cb) = hi1;
            *(uint32_t*)(sm + AT2_PL + r1*144 + cb) = lo1;
        }
        sum0 += __shfl_xor_sync(0xffffffffu, sum0, 1);
        sum0 += __shfl_xor_sync(0xffffffffu, sum0, 2);
        sum1 += __shfl_xor_sync(0xffffffffu, sum1, 1);
        sum1 += __shfl_xor_sync(0xffffffffu, sum1, 2);
        if (t == 0) {
            smf[ATS_PSM/4 + ch*128 + r0] = sum0;
            smf[ATS_PSM/4 + ch*128 + r1] = sum1;
        }
        if (ch == 0 && t == 0) {
            smf[ATS_SC/4 + r0] = __expf(mo0 - mn0);
            smf[ATS_SC/4 + r1] = __expf(mo1 - mn1);
            smf[ATS_M/4 + (par ^ 1)*128 + r0] = mn0;
            smf[ATS_M/4 + (par ^ 1)*128 + r1] = mn1;
        }
        CPA_WAIT(1);                           // V(kt) ready (K prefetch stays)
        __syncthreads();

        // ---- l update (owner warps) ----
        if (ch == 0 && t == 0) {
            smf[ATS_L/4 + r0] = smf[ATS_L/4 + r0] * smf[ATS_SC/4 + r0]
                              + smf[ATS_PSM/4 + r0] + smf[ATS_PSM/4 + 128 + r0];
            smf[ATS_L/4 + r1] = smf[ATS_L/4 + r1] * smf[ATS_SC/4 + r1]
                              + smf[ATS_PSM/4 + r1] + smf[ATS_PSM/4 + 128 + r1];
        }

        // ---- PV: rescale O, O += P @ V ----
        {
            const float f0 = smf[ATS_SC/4 + mp + g];
            const float f1 = smf[ATS_SC/4 + mp + 8 + g];
            const float f2 = smf[ATS_SC/4 + mp + 16 + g];
            const float f3 = smf[ATS_SC/4 + mp + 24 + g];
            #pragma unroll
            for (int nt = 0; nt < 8; nt++) {
                o[nt][0] *= f0; o[nt][1] *= f0;
                o[nt][2] *= f1; o[nt][3] *= f1;
                o[8+nt][0] *= f2; o[8+nt][1] *= f2;
                o[8+nt][2] *= f3; o[8+nt][3] *= f3;
            }
        }
        #pragma unroll
        for (int ks = 0; ks < 4; ks++) {
            uint32_t pah[2][4], pal[2][4];
            #pragma unroll
            for (int mt = 0; mt < 2; mt++) {
                LDMX4(pah[mt], a_addr(smb + AT2_PH, mp + mt*16, ks*32, lane, 144));
                LDMX4(pal[mt], a_addr(smb + AT2_PL, mp + mt*16, ks*32, lane, 144));
            }
            #pragma unroll
            for (int ntp = 0; ntp < 4; ntp++) {
                uint32_t vh4[4], vl4[4];
                const uint32_t va = smb + AT2_VH +
                    (uint32_t)(ks*16 + (lane & 7) + (((lane >> 3) & 1) << 3)) * 528
                    + (np + ntp*16 + ((lane >> 4) << 3)) * 2;
                LDMX4T(vh4, va);
                LDMX4T(vl4, va + (AT2_VL - AT2_VH));
                MMA3(o[2*ntp],     pah[0], pal[0], vh4,     vl4);
                MMA3(o[2*ntp + 1], pah[0], pal[0], vh4 + 2, vl4 + 2);
                MMA3(o[8 + 2*ntp],     pah[1], pal[1], vh4,     vl4);
                MMA3(o[8 + 2*ntp + 1], pah[1], pal[1], vh4 + 2, vl4 + 2);
            }
        }
    }

    // ---- normalize + store ----
    __syncthreads();
    #pragma unroll
    for (int mt = 0; mt < 2; mt++) {
        const int r = mp + mt*16 + g;
        const float i0 = 1.f / smf[ATS_L/4 + r];
        const float i1 = 1.f / smf[ATS_L/4 + r + 8];
        #pragma unroll
        for (int nt = 0; nt < 8; nt++) {
            const int c = d0 + np + nt*8 + 2*t;
            float2 v0 = make_float2(o[mt*8+nt][0]*i0, o[mt*8+nt][1]*i0);
            float2 v1 = make_float2(o[mt*8+nt][2]*i1, o[mt*8+nt][3]*i1);
            *(float2*)(out + (tok0 + q0 + r)     * EMB + c) = v0;
            *(float2*)(out + (tok0 + q0 + r + 8) * EMB + c) = v1;
        }
    }
}

// ===========================================================================
extern "C" void kernel_launch(void* const* d_in, const int* in_sizes, int n_in,
                              void* d_out, int out_size)
{
    const float* x  = (const float*)d_in[0];
    const float* Wk = (const float*)d_in[1];
    const float* Wq = (const float*)d_in[2];
    const float* Wv = (const float*)d_in[3];
    float* out = (float*)d_out;

    __nv_bfloat16 *Qh, *Ql, *Kh, *Kl, *Vh, *Vl;
    cudaGetSymbolAddress((void**)&Qh, g_Qh);
    cudaGetSymbolAddress((void**)&Ql, g_Ql);
    cudaGetSymbolAddress((void**)&Kh, g_Kh);
    cudaGetSymbolAddress((void**)&Kl, g_Kl);
    cudaGetSymbolAddress((void**)&Vh, g_Vh);
    cudaGetSymbolAddress((void**)&Vl, g_Vl);

    cudaFuncSetAttribute(qkproj_mma, cudaFuncAttributeMaxDynamicSharedMemorySize, PJ_SMEM);
    cudaFuncSetAttribute(vproj_tf32, cudaFuncAttributeMaxDynamicSharedMemorySize, VP_SMEM);
    cudaFuncSetAttribute(attn_fused, cudaFuncAttributeMaxDynamicSharedMemorySize, AT2_SMEM);

    qkproj_mma<<<dim3(1, BT/128), 256, PJ_SMEM>>>(x, Wk, Wq, Kh, Kl, Qh, Ql);
    vproj_tf32<<<dim3(EMB/128, BT/128), 256, VP_SMEM>>>(x, Wv, Vh, Vl);
    attn_fused<<<dim3(EMB/256, SEQ/128, BATCH), 512, AT2_SMEM>>>(
        Qh, Ql, Kh, Kl, Vh, Vl, out);
}